// round 3
// baseline (speedup 1.0000x reference)
#include <cuda_runtime.h>

typedef unsigned long long ull;

#define BATCH 16
#define CHAN  64
#define S     4096
#define S4    1024
#define C8    8
#define C2    32
#define TPB   512

// Scratch: phi and g, pre-transposed to [b][t][oc]
__device__ float g_phiT[BATCH * S4 * C8];   // 512 KB
__device__ float g_gT[BATCH * S4 * C2];     // 2 MB

// ---- packed f32x2 helpers (Blackwell FFMA2) ----
__device__ __forceinline__ ull pack2(float a, float b) {
    ull r; asm("mov.b64 %0, {%1, %2};" : "=l"(r) : "f"(a), "f"(b)); return r;
}
__device__ __forceinline__ void unpack2(ull v, float& a, float& b) {
    asm("mov.b64 {%0, %1}, %2;" : "=f"(a), "=f"(b) : "l"(v));
}
__device__ __forceinline__ ull ffma2(ull a, ull b, ull c) {
    ull d; asm("fma.rn.f32x2 %0, %1, %2, %3;" : "=l"(d) : "l"(a), "l"(b), "l"(c)); return d;
}
__device__ __forceinline__ ull d2u(double d) { return __double_as_longlong(d); }

// ---------------------------------------------------------------------------
// Kernel A: fused 1x1 conv (phi: 8ch, g: 32ch) + 2x2 maxpool, transposed out.
// ---------------------------------------------------------------------------
__global__ void __launch_bounds__(256) convpool_kernel(
    const float* __restrict__ x,
    const float* __restrict__ w_phi,
    const float* __restrict__ w_g)
{
    int idx = blockIdx.x * 256 + threadIdx.x;
    int t   = idx & 1023;
    int grp = (idx >> 10) % 10;
    int b   = idx / (1024 * 10);
    if (b >= BATCH) return;

    int h2  = t >> 5, w2 = t & 31;
    int p00 = (h2 * 2) * 64 + w2 * 2;
    const float* xb = x + (size_t)b * CHAN * S;

    float acc[4][4];
#pragma unroll
    for (int j = 0; j < 4; j++)
        acc[j][0] = acc[j][1] = acc[j][2] = acc[j][3] = 0.f;

    int oc0 = grp * 4;
    const float* W = (oc0 < 8) ? (w_phi + oc0 * CHAN)
                               : (w_g + (oc0 - 8) * CHAN);

#pragma unroll 4
    for (int c = 0; c < CHAN; c++) {
        const float* xc = xb + c * S;
        float2 a0 = *(const float2*)(xc + p00);
        float2 a1 = *(const float2*)(xc + p00 + 64);
#pragma unroll
        for (int j = 0; j < 4; j++) {
            float w = __ldg(W + j * CHAN + c);
            acc[j][0] += w * a0.x;
            acc[j][1] += w * a0.y;
            acc[j][2] += w * a1.x;
            acc[j][3] += w * a1.y;
        }
    }

    float4 r;
    float* rp = (float*)&r;
#pragma unroll
    for (int j = 0; j < 4; j++)
        rp[j] = fmaxf(fmaxf(acc[j][0], acc[j][1]), fmaxf(acc[j][2], acc[j][3]));

    if (oc0 < 8)
        *(float4*)(g_phiT + (size_t)b * S4 * C8 + t * C8 + oc0) = r;
    else
        *(float4*)(g_gT + (size_t)b * S4 * C2 + t * C2 + (oc0 - 8)) = r;
}

// ---------------------------------------------------------------------------
// Kernel B: fused attention, f32x2-packed, ONE query/thread, 512 thr/block.
// Single-pass softmax in the exp2 domain (log2e folded into w_theta).
// Grid: 16 batches * 8 tiles = 128 blocks -> one wave, 16 warps/SM.
// ---------------------------------------------------------------------------
__global__ void __launch_bounds__(TPB) attn_kernel(
    const float* __restrict__ x,
    const float* __restrict__ w_theta,
    const float* __restrict__ w_o,
    const float* __restrict__ gamma_p,
    float* __restrict__ out)
{
    extern __shared__ float sm[];
    float* phi_s = sm;                    // 1024*8  floats
    float* g_s   = sm + S4 * C8;          // 1024*32 floats
    float* wth_s = g_s + S4 * C2;         // 64*8 floats, transposed [c][d], *log2e
    float* wo_s  = wth_s + CHAN * C8;     // 64*32 floats [co][k]

    int tid = threadIdx.x;
    int b   = blockIdx.x >> 3;
    int s   = (blockIdx.x & 7) * TPB + tid;

    // --- fill smem ---
    {
        const float4* src = (const float4*)(g_phiT + (size_t)b * S4 * C8);
        float4* dst = (float4*)phi_s;
        for (int i = tid; i < S4 * C8 / 4; i += TPB) dst[i] = src[i];
    }
    {
        const float4* src = (const float4*)(g_gT + (size_t)b * S4 * C2);
        float4* dst = (float4*)g_s;
        for (int i = tid; i < S4 * C2 / 4; i += TPB) dst[i] = src[i];
    }
    for (int i = tid; i < CHAN * C8; i += TPB) {   // transpose + fold log2e
        int c = i >> 3, d = i & 7;
        wth_s[i] = w_theta[d * CHAN + c] * 1.4426950408889634f;
    }
    {
        const float4* src = (const float4*)w_o;
        float4* dst = (float4*)wo_s;
        for (int i = tid; i < CHAN * C2 / 4; i += TPB) dst[i] = src[i];
    }
    __syncthreads();

    // --- theta[8] packed over d: th2[j] = (th[2j], th[2j+1]) (log2-scaled) ---
    ull th2[4];
#pragma unroll
    for (int j = 0; j < 4; j++) th2[j] = 0ull;
    {
        const float* xb = x + (size_t)b * CHAN * S + s;
        for (int c = 0; c < CHAN; c++) {
            float xc = xb[(size_t)c * S];
            double2 wA = *(const double2*)(wth_s + c * 8);
            double2 wB = *(const double2*)(wth_s + c * 8 + 4);
            ull xp = pack2(xc, xc);
            th2[0] = ffma2(xp, d2u(wA.x), th2[0]);
            th2[1] = ffma2(xp, d2u(wA.y), th2[1]);
            th2[2] = ffma2(xp, d2u(wB.x), th2[2]);
            th2[3] = ffma2(xp, d2u(wB.y), th2[3]);
        }
    }

    // --- single pass over keys: score -> exp2 -> accumulate g (packed) ---
    float l = 0.f;
    ull o2[16];
#pragma unroll
    for (int k = 0; k < 16; k++) o2[k] = 0ull;

#pragma unroll 2
    for (int t = 0; t < S4; t++) {
        double2 pA = *(const double2*)(phi_s + t * 8);
        double2 pB = *(const double2*)(phi_s + t * 8 + 4);

        ull a = ffma2(th2[0], d2u(pA.x), 0ull);
        a = ffma2(th2[1], d2u(pA.y), a);
        a = ffma2(th2[2], d2u(pB.x), a);
        a = ffma2(th2[3], d2u(pB.y), a);

        float lo, hi;
        unpack2(a, lo, hi);
        float p = exp2f(lo + hi);     // scores already log2-scaled
        l += p;
        ull pp = pack2(p, p);

        const double2* gt = (const double2*)(g_s + t * 32);
#pragma unroll
        for (int j = 0; j < 8; j++) {
            double2 gv = gt[j];
            o2[2 * j]     = ffma2(pp, d2u(gv.x), o2[2 * j]);
            o2[2 * j + 1] = ffma2(pp, d2u(gv.y), o2[2 * j + 1]);
        }
    }

    float n0 = gamma_p[0] / l;

    // --- epilogue: out = n0 * (w_o @ o) + x, packed over k ---
    const float* xr = x + (size_t)b * CHAN * S + s;
    float* orow = out + (size_t)b * CHAN * S + s;
    for (int co = 0; co < CHAN; co++) {
        const double2* wr = (const double2*)(wo_s + co * 32);
        ull acc = 0ull;
#pragma unroll
        for (int j = 0; j < 8; j++) {
            double2 wv = wr[j];
            acc = ffma2(d2u(wv.x), o2[2 * j], acc);
            acc = ffma2(d2u(wv.y), o2[2 * j + 1], acc);
        }
        float lo, hi;
        unpack2(acc, lo, hi);
        orow[(size_t)co * S] = n0 * (lo + hi) + xr[(size_t)co * S];
    }
}

// ---------------------------------------------------------------------------
extern "C" void kernel_launch(void* const* d_in, const int* in_sizes, int n_in,
                              void* d_out, int out_size)
{
    const float* x       = (const float*)d_in[0];
    const float* w_theta = (const float*)d_in[1];
    const float* w_phi   = (const float*)d_in[2];
    const float* w_g     = (const float*)d_in[3];
    const float* w_o     = (const float*)d_in[4];
    const float* gamma   = (const float*)d_in[5];
    float* out = (float*)d_out;

    convpool_kernel<<<640, 256>>>(x, w_phi, w_g);

    int smem_bytes = (S4 * C8 + S4 * C2 + CHAN * C8 + CHAN * C2) * (int)sizeof(float);
    cudaFuncSetAttribute(attn_kernel,
                         cudaFuncAttributeMaxDynamicSharedMemorySize, smem_bytes);
    attn_kernel<<<128, TPB, smem_bytes>>>(x, w_theta, w_o, gamma, out);
}

// round 4
// speedup vs baseline: 1.0250x; 1.0250x over previous
#include <cuda_runtime.h>

typedef unsigned long long ull;

#define BATCH 16
#define CHAN  64
#define S     4096
#define S4    1024
#define KH    512          // keys per half
#define C8    8
#define C2    32

// Scratch (no cudaMalloc allowed)
__device__ float g_phiT[BATCH * S4 * C8];        // 512 KB  [b][t][8]
__device__ float g_gT[BATCH * S4 * C2];          // 2 MB    [b][t][32]
__device__ float g_thetaT[BATCH * S * C8];       // 2 MB    [b][s][8], *log2e
__device__ float g_opart[2 * BATCH * S * C2];    // 16 MB   [kh][b][s][32]
__device__ float g_lpart[2 * BATCH * S];         // 512 KB  [kh][b][s]

// ---- packed f32x2 helpers (Blackwell FFMA2) ----
__device__ __forceinline__ ull pack2(float a, float b) {
    ull r; asm("mov.b64 %0, {%1, %2};" : "=l"(r) : "f"(a), "f"(b)); return r;
}
__device__ __forceinline__ void unpack2(ull v, float& a, float& b) {
    asm("mov.b64 {%0, %1}, %2;" : "=f"(a), "=f"(b) : "l"(v));
}
__device__ __forceinline__ ull ffma2(ull a, ull b, ull c) {
    ull d; asm("fma.rn.f32x2 %0, %1, %2, %3;" : "=l"(d) : "l"(a), "l"(b), "l"(c)); return d;
}
__device__ __forceinline__ ull fadd2(ull a, ull b) {
    ull d; asm("add.rn.f32x2 %0, %1, %2;" : "=l"(d) : "l"(a), "l"(b)); return d;
}
__device__ __forceinline__ ull d2u(double d) { return __double_as_longlong(d); }

// ---------------------------------------------------------------------------
// Kernel A: fused 1x1 conv (phi 8ch, g 32ch) + 2x2 maxpool, transposed out.
// ---------------------------------------------------------------------------
__global__ void __launch_bounds__(256) convpool_kernel(
    const float* __restrict__ x,
    const float* __restrict__ w_phi,
    const float* __restrict__ w_g)
{
    int idx = blockIdx.x * 256 + threadIdx.x;
    int t   = idx & 1023;
    int grp = (idx >> 10) % 10;
    int b   = idx / (1024 * 10);
    if (b >= BATCH) return;

    int h2  = t >> 5, w2 = t & 31;
    int p00 = (h2 * 2) * 64 + w2 * 2;
    const float* xb = x + (size_t)b * CHAN * S;

    float acc[4][4];
#pragma unroll
    for (int j = 0; j < 4; j++)
        acc[j][0] = acc[j][1] = acc[j][2] = acc[j][3] = 0.f;

    int oc0 = grp * 4;
    const float* W = (oc0 < 8) ? (w_phi + oc0 * CHAN)
                               : (w_g + (oc0 - 8) * CHAN);

#pragma unroll 4
    for (int c = 0; c < CHAN; c++) {
        const float* xc = xb + c * S;
        float2 a0 = *(const float2*)(xc + p00);
        float2 a1 = *(const float2*)(xc + p00 + 64);
#pragma unroll
        for (int j = 0; j < 4; j++) {
            float w = __ldg(W + j * CHAN + c);
            acc[j][0] += w * a0.x;
            acc[j][1] += w * a0.y;
            acc[j][2] += w * a1.x;
            acc[j][3] += w * a1.y;
        }
    }

    float4 r;
    float* rp = (float*)&r;
#pragma unroll
    for (int j = 0; j < 4; j++)
        rp[j] = fmaxf(fmaxf(acc[j][0], acc[j][1]), fmaxf(acc[j][2], acc[j][3]));

    if (oc0 < 8)
        *(float4*)(g_phiT + (size_t)b * S4 * C8 + t * C8 + oc0) = r;
    else
        *(float4*)(g_gT + (size_t)b * S4 * C2 + t * C2 + (oc0 - 8)) = r;
}

// ---------------------------------------------------------------------------
// Kernel A2: theta = (log2e * w_theta) @ x, full res, transposed [b][s][8].
// ---------------------------------------------------------------------------
__global__ void __launch_bounds__(256) theta_kernel(
    const float* __restrict__ x,
    const float* __restrict__ w_theta)
{
    int idx = blockIdx.x * 256 + threadIdx.x;   // 65536 threads
    int s = idx & (S - 1);
    int b = idx >> 12;

    const float* xb = x + (size_t)b * CHAN * S + s;
    float acc[8];
#pragma unroll
    for (int d = 0; d < 8; d++) acc[d] = 0.f;

#pragma unroll 4
    for (int c = 0; c < CHAN; c++) {
        float xc = xb[(size_t)c * S];
#pragma unroll
        for (int d = 0; d < 8; d++)
            acc[d] += __ldg(w_theta + d * CHAN + c) * xc;
    }

    float4* dst = (float4*)(g_thetaT + (size_t)idx * 8);
    const float L2E = 1.4426950408889634f;
    dst[0] = make_float4(acc[0] * L2E, acc[1] * L2E, acc[2] * L2E, acc[3] * L2E);
    dst[1] = make_float4(acc[4] * L2E, acc[5] * L2E, acc[6] * L2E, acc[7] * L2E);
}

// ---------------------------------------------------------------------------
// Kernel B: attention partials over one key-half. f32x2-packed, 2 q/thread.
// Grid: 16 b x 2 kh x 8 qt = 256 blocks, 256 thr, 80KB smem -> 2 CTAs/SM.
// Writes unnormalized l and o (linear-combinable: no max shift).
// ---------------------------------------------------------------------------
__global__ void __launch_bounds__(256, 2) attn_kernel(int dummy)
{
    extern __shared__ float sm[];
    float* phi_s = sm;               // 512*8  floats (16 KB)
    float* g_s   = sm + KH * C8;     // 512*32 floats (64 KB)

    int tid = threadIdx.x;
    int b   = blockIdx.x >> 4;
    int kh  = (blockIdx.x >> 3) & 1;
    int qt  = blockIdx.x & 7;
    int q0  = qt * 512 + tid;        // second query: q0 + 256

    // --- fill smem (coalesced float4 copies of this key half) ---
    {
        const float4* src = (const float4*)(g_phiT + ((size_t)b * S4 + kh * KH) * C8);
        float4* dst = (float4*)phi_s;
        for (int i = tid; i < KH * C8 / 4; i += 256) dst[i] = src[i];
    }
    {
        const float4* src = (const float4*)(g_gT + ((size_t)b * S4 + kh * KH) * C2);
        float4* dst = (float4*)g_s;
        for (int i = tid; i < KH * C2 / 4; i += 256) dst[i] = src[i];
    }
    __syncthreads();

    // --- load precomputed theta (log2-scaled), packed pairs over d ---
    ull th2[2][4];
    {
        const ull* t0 = (const ull*)(g_thetaT + ((size_t)b * S + q0) * 8);
        const ull* t1 = (const ull*)(g_thetaT + ((size_t)b * S + q0 + 256) * 8);
#pragma unroll
        for (int j = 0; j < 4; j++) { th2[0][j] = t0[j]; th2[1][j] = t1[j]; }
    }

    // --- key-half loop: score -> exp2 -> accumulate g (packed) ---
    float l0 = 0.f, l1 = 0.f;
    ull o2[2][16];
#pragma unroll
    for (int k = 0; k < 16; k++) o2[0][k] = o2[1][k] = 0ull;

#pragma unroll 2
    for (int t = 0; t < KH; t++) {
        double2 pA = *(const double2*)(phi_s + t * 8);
        double2 pB = *(const double2*)(phi_s + t * 8 + 4);
        ull ph0 = d2u(pA.x), ph1 = d2u(pA.y), ph2 = d2u(pB.x), ph3 = d2u(pB.y);

        ull a0 = ffma2(th2[0][0], ph0, 0ull);
        ull a1 = ffma2(th2[1][0], ph0, 0ull);
        a0 = ffma2(th2[0][1], ph1, a0);
        a1 = ffma2(th2[1][1], ph1, a1);
        a0 = ffma2(th2[0][2], ph2, a0);
        a1 = ffma2(th2[1][2], ph2, a1);
        a0 = ffma2(th2[0][3], ph3, a0);
        a1 = ffma2(th2[1][3], ph3, a1);

        float lo, hi;
        unpack2(a0, lo, hi);
        float p0 = exp2f(lo + hi);
        unpack2(a1, lo, hi);
        float p1 = exp2f(lo + hi);
        l0 += p0;
        l1 += p1;
        ull pp0 = pack2(p0, p0);
        ull pp1 = pack2(p1, p1);

        const double2* gt = (const double2*)(g_s + t * 32);
#pragma unroll
        for (int j = 0; j < 8; j++) {
            double2 gv = gt[j];
            ull ga = d2u(gv.x), gb = d2u(gv.y);
            o2[0][2 * j]     = ffma2(pp0, ga, o2[0][2 * j]);
            o2[0][2 * j + 1] = ffma2(pp0, gb, o2[0][2 * j + 1]);
            o2[1][2 * j]     = ffma2(pp1, ga, o2[1][2 * j]);
            o2[1][2 * j + 1] = ffma2(pp1, gb, o2[1][2 * j + 1]);
        }
    }

    // --- write partials (packed pairs stored verbatim) ---
    size_t base = ((size_t)kh * BATCH + b) * S;
    ull* op0 = (ull*)(g_opart + (base + q0) * C2);
    ull* op1 = (ull*)(g_opart + (base + q0 + 256) * C2);
#pragma unroll
    for (int jj = 0; jj < 8; jj++) {
        ((ulonglong2*)op0)[jj] = make_ulonglong2(o2[0][2 * jj], o2[0][2 * jj + 1]);
        ((ulonglong2*)op1)[jj] = make_ulonglong2(o2[1][2 * jj], o2[1][2 * jj + 1]);
    }
    g_lpart[base + q0] = l0;
    g_lpart[base + q0 + 256] = l1;
}

// ---------------------------------------------------------------------------
// Kernel C: combine halves + w_o epilogue + residual. One thread per query.
// ---------------------------------------------------------------------------
__global__ void __launch_bounds__(256) reduce_kernel(
    const float* __restrict__ x,
    const float* __restrict__ w_o,
    const float* __restrict__ gamma_p,
    float* __restrict__ out)
{
    __shared__ float wo_s[CHAN * C2];
    int tid = threadIdx.x;
    for (int i = tid; i < CHAN * C2 / 4; i += 256)
        ((float4*)wo_s)[i] = ((const float4*)w_o)[i];
    __syncthreads();

    int idx = blockIdx.x * 256 + tid;   // 65536 queries
    int s = idx & (S - 1);
    int b = idx >> 12;

    const ulonglong2* pa = (const ulonglong2*)(g_opart + ((size_t)(0 * BATCH + b) * S + s) * C2);
    const ulonglong2* pb = (const ulonglong2*)(g_opart + ((size_t)(1 * BATCH + b) * S + s) * C2);
    ull o2[16];
#pragma unroll
    for (int jj = 0; jj < 8; jj++) {
        ulonglong2 va = pa[jj];
        ulonglong2 vb = pb[jj];
        o2[2 * jj]     = fadd2(va.x, vb.x);
        o2[2 * jj + 1] = fadd2(va.y, vb.y);
    }
    float l = g_lpart[(size_t)b * S + s] + g_lpart[(size_t)(BATCH + b) * S + s];
    float n0 = gamma_p[0] / l;

    const float* xr = x + (size_t)b * CHAN * S + s;
    float* orow = out + (size_t)b * CHAN * S + s;
    for (int co = 0; co < CHAN; co++) {
        const double2* wr = (const double2*)(wo_s + co * 32);
        ull acc = 0ull;
#pragma unroll
        for (int j = 0; j < 8; j++) {
            double2 wv = wr[j];
            acc = ffma2(d2u(wv.x), o2[2 * j], acc);
            acc = ffma2(d2u(wv.y), o2[2 * j + 1], acc);
        }
        float lo, hi;
        unpack2(acc, lo, hi);
        orow[(size_t)co * S] = n0 * (lo + hi) + xr[(size_t)co * S];
    }
}

// ---------------------------------------------------------------------------
extern "C" void kernel_launch(void* const* d_in, const int* in_sizes, int n_in,
                              void* d_out, int out_size)
{
    const float* x       = (const float*)d_in[0];
    const float* w_theta = (const float*)d_in[1];
    const float* w_phi   = (const float*)d_in[2];
    const float* w_g     = (const float*)d_in[3];
    const float* w_o     = (const float*)d_in[4];
    const float* gamma   = (const float*)d_in[5];
    float* out = (float*)d_out;

    convpool_kernel<<<640, 256>>>(x, w_phi, w_g);
    theta_kernel<<<256, 256>>>(x, w_theta);

    int smem_bytes = (KH * C8 + KH * C2) * (int)sizeof(float);   // 81920
    cudaFuncSetAttribute(attn_kernel,
                         cudaFuncAttributeMaxDynamicSharedMemorySize, smem_bytes);
    attn_kernel<<<256, 256, smem_bytes>>>(0);

    reduce_kernel<<<256, 256>>>(x, w_o, gamma, out);
}

// round 8
// speedup vs baseline: 2.6393x; 2.5749x over previous
#include <cuda_runtime.h>
#include <cuda_fp16.h>

typedef unsigned long long ull;
typedef unsigned int u32;

#define BATCH 16
#define CHAN  64
#define S     4096
#define S4    1024

__device__ __align__(16) __half g_phi16[BATCH * S4 * 8];  // [b][t][8]
__device__ __align__(16) __half g_g16[BATCH * 32 * S4];   // [b][oc][t]
__device__ __align__(16) __half g_th16[BATCH * S * 8];    // [b][s][8] *log2e

// ---------------- helpers ----------------
__device__ __forceinline__ float ex2f(float a) {
    float r; asm("ex2.approx.ftz.f32 %0, %1;" : "=f"(r) : "f"(a)); return r;
}
__device__ __forceinline__ u32 f16x2_of(float lo, float hi) {
    u32 r; asm("cvt.rn.f16x2.f32 %0, %1, %2;" : "=r"(r) : "f"(hi), "f"(lo)); return r;
}
__device__ __forceinline__ u32 h2u(__half2 h) { return *reinterpret_cast<u32*>(&h); }
__device__ __forceinline__ ull pack2(float a, float b) {
    ull r; asm("mov.b64 %0, {%1, %2};" : "=l"(r) : "f"(a), "f"(b)); return r;
}
__device__ __forceinline__ void unpack2(ull v, float& a, float& b) {
    asm("mov.b64 {%0, %1}, %2;" : "=f"(a), "=f"(b) : "l"(v));
}
__device__ __forceinline__ ull ffma2(ull a, ull b, ull c) {
    ull d; asm("fma.rn.f32x2 %0, %1, %2, %3;" : "=l"(d) : "l"(a), "l"(b), "l"(c)); return d;
}
__device__ __forceinline__ ull d2u(double d) { return __double_as_longlong(d); }

__device__ __forceinline__ void mma_16n8k8(float* c, u32 a0, u32 a1, u32 b0) {
    asm volatile("mma.sync.aligned.m16n8k8.row.col.f32.f16.f16.f32 "
        "{%0,%1,%2,%3}, {%4,%5}, {%6}, {%0,%1,%2,%3};"
        : "+f"(c[0]), "+f"(c[1]), "+f"(c[2]), "+f"(c[3])
        : "r"(a0), "r"(a1), "r"(b0));
}
__device__ __forceinline__ void mma_16n8k16(float* c, u32 a0, u32 a1, u32 a2, u32 a3,
                                            u32 b0, u32 b1) {
    asm volatile("mma.sync.aligned.m16n8k16.row.col.f32.f16.f16.f32 "
        "{%0,%1,%2,%3}, {%4,%5,%6,%7}, {%8,%9}, {%0,%1,%2,%3};"
        : "+f"(c[0]), "+f"(c[1]), "+f"(c[2]), "+f"(c[3])
        : "r"(a0), "r"(a1), "r"(a2), "r"(a3), "r"(b0), "r"(b1));
}

// smem byte offsets (dynamic)
#define PHI_OFF 0                      // 1024*8 halves          = 16384
#define G_OFF   16384                  // 32 rows * 2064 B       = 66048
#define GROW    2064                   // 1024 halves + 8 pad
#define O_OFF   82432                  // 128 q * 34 floats      = 17408
#define OROW    34
#define L_OFF   99840                  // 128 floats             = 512
#define WO_OFF  100352                 // 64*32 floats           = 8192
#define SMEM_REQ 108544

// ---------------------------------------------------------------------------
// Prep A: fused 1x1 conv (phi 8ch, g 32ch) + 2x2 maxpool -> fp16 staging.
// ---------------------------------------------------------------------------
__global__ void __launch_bounds__(256) convpool_kernel(
    const float* __restrict__ x, const float* __restrict__ w_phi,
    const float* __restrict__ w_g)
{
    int idx = blockIdx.x * 256 + threadIdx.x;
    int t = idx & 1023, grp = (idx >> 10) % 10, b = idx / (1024 * 10);
    if (b >= BATCH) return;
    int p00 = ((t >> 5) * 2) * 64 + (t & 31) * 2;
    const float* xb = x + (size_t)b * CHAN * S;
    float acc[4][4];
#pragma unroll
    for (int j = 0; j < 4; j++)
        acc[j][0] = acc[j][1] = acc[j][2] = acc[j][3] = 0.f;
    int oc0 = grp * 4;
    const float* W = (oc0 < 8) ? (w_phi + oc0 * CHAN) : (w_g + (oc0 - 8) * CHAN);
#pragma unroll 4
    for (int c = 0; c < CHAN; c++) {
        const float* xc = xb + c * S;
        float2 a0 = *(const float2*)(xc + p00);
        float2 a1 = *(const float2*)(xc + p00 + 64);
#pragma unroll
        for (int j = 0; j < 4; j++) {
            float w = __ldg(W + j * CHAN + c);
            acc[j][0] += w * a0.x; acc[j][1] += w * a0.y;
            acc[j][2] += w * a1.x; acc[j][3] += w * a1.y;
        }
    }
    float r[4];
#pragma unroll
    for (int j = 0; j < 4; j++)
        r[j] = fmaxf(fmaxf(acc[j][0], acc[j][1]), fmaxf(acc[j][2], acc[j][3]));
    if (oc0 < 8) {
        uint2 u;
        u.x = h2u(__floats2half2_rn(r[0], r[1]));
        u.y = h2u(__floats2half2_rn(r[2], r[3]));
        *(uint2*)(g_phi16 + (size_t)(b * S4 + t) * 8 + oc0) = u;
    } else {
        int oc = oc0 - 8;
#pragma unroll
        for (int j = 0; j < 4; j++)
            g_g16[((size_t)b * 32 + oc + j) * S4 + t] = __float2half(r[j]);
    }
}

// ---------------------------------------------------------------------------
// Prep A2: theta = w_theta @ x, x log2e, fp16, [b][s][8].
// ---------------------------------------------------------------------------
__global__ void __launch_bounds__(256) theta_kernel(
    const float* __restrict__ x, const float* __restrict__ w_theta)
{
    int idx = blockIdx.x * 256 + threadIdx.x;
    int s = idx & (S - 1), b = idx >> 12;
    const float* xb = x + (size_t)b * CHAN * S + s;
    float acc[8];
#pragma unroll
    for (int d = 0; d < 8; d++) acc[d] = 0.f;
#pragma unroll 4
    for (int c = 0; c < CHAN; c++) {
        float xc = xb[(size_t)c * S];
#pragma unroll
        for (int d = 0; d < 8; d++)
            acc[d] += __ldg(w_theta + d * CHAN + c) * xc;
    }
    const float L2E = 1.4426950408889634f;
    uint4 o;
    o.x = h2u(__floats2half2_rn(acc[0] * L2E, acc[1] * L2E));
    o.y = h2u(__floats2half2_rn(acc[2] * L2E, acc[3] * L2E));
    o.z = h2u(__floats2half2_rn(acc[4] * L2E, acc[5] * L2E));
    o.w = h2u(__floats2half2_rn(acc[6] * L2E, acc[7] * L2E));
    *(uint4*)(g_th16 + (size_t)idx * 8) = o;
}

// ---------------------------------------------------------------------------
// Attention: warp-level HMMA flash, TWO-PASS (per-query max, then exp+PV).
// Warp = 16 queries; CTA = 128 queries; grid 512 CTAs x 256 thr, 2 CTAs/SM.
// ---------------------------------------------------------------------------
__global__ void __launch_bounds__(256, 2) attn_hmma(
    const float* __restrict__ x, const float* __restrict__ w_o,
    const float* __restrict__ gamma_p, float* __restrict__ out)
{
    extern __shared__ char smem[];
    __half* phi_s = (__half*)(smem + PHI_OFF);
    float*  o_s   = (float*)(smem + O_OFF);
    float*  l_s   = (float*)(smem + L_OFF);
    float*  wo_s  = (float*)(smem + WO_OFF);

    const int tid = threadIdx.x;
    const int w   = tid >> 5;
    const int lane = tid & 31;
    const int g   = lane >> 2;
    const int tig = lane & 3;
    const int b   = blockIdx.x >> 5;
    const int q0b = (blockIdx.x & 31) * 128;
    const int qw  = q0b + w * 16;

    // --- fill smem ---
    {
        const uint4* src = (const uint4*)(g_phi16 + (size_t)b * S4 * 8);
        uint4* dst = (uint4*)phi_s;
        for (int i = tid; i < 1024; i += 256) dst[i] = src[i];
    }
    for (int i = tid; i < 4096; i += 256) {
        int oc = i >> 7, j = i & 127;
        uint4 v = *(const uint4*)(g_g16 + ((size_t)b * 32 + oc) * S4 + j * 8);
        *(uint4*)(smem + G_OFF + oc * GROW + j * 16) = v;
    }
    for (int i = tid; i < 512; i += 256)
        ((float4*)wo_s)[i] = ((const float4*)w_o)[i];
    __syncthreads();

    // --- theta A-fragments ---
    u32 tA0 = *(const u32*)(g_th16 + (size_t)(b * S + qw + g) * 8 + tig * 2);
    u32 tA1 = *(const u32*)(g_th16 + (size_t)(b * S + qw + 8 + g) * 8 + tig * 2);

    // ---- pass 1: per-query row max of scores ----
    float m0 = -1e30f, m1 = -1e30f;
#pragma unroll 4
    for (int cb = 0; cb < S4; cb += 16) {
        u32 bA = *(const u32*)(phi_s + (cb + g) * 8 + tig * 2);
        u32 bB = *(const u32*)(phi_s + (cb + 8 + g) * 8 + tig * 2);
        float c0[4] = {0.f, 0.f, 0.f, 0.f};
        float c1[4] = {0.f, 0.f, 0.f, 0.f};
        mma_16n8k8(c0, tA0, tA1, bA);
        mma_16n8k8(c1, tA0, tA1, bB);
        m0 = fmaxf(m0, fmaxf(fmaxf(c0[0], c0[1]), fmaxf(c1[0], c1[1])));
        m1 = fmaxf(m1, fmaxf(fmaxf(c0[2], c0[3]), fmaxf(c1[2], c1[3])));
    }
    m0 = fmaxf(m0, __shfl_xor_sync(0xFFFFFFFF, m0, 1));
    m0 = fmaxf(m0, __shfl_xor_sync(0xFFFFFFFF, m0, 2));
    m1 = fmaxf(m1, __shfl_xor_sync(0xFFFFFFFF, m1, 1));
    m1 = fmaxf(m1, __shfl_xor_sync(0xFFFFFFFF, m1, 2));

    // ---- pass 2: p = exp2(s - m) in (0,1], accumulate l and O ----
    float o[4][4];
#pragma unroll
    for (int nt = 0; nt < 4; nt++)
#pragma unroll
        for (int j = 0; j < 4; j++) o[nt][j] = 0.f;
    float l0 = 0.f, l1 = 0.f;

#pragma unroll 2
    for (int cb = 0; cb < S4; cb += 16) {
        u32 bA = *(const u32*)(phi_s + (cb + g) * 8 + tig * 2);
        u32 bB = *(const u32*)(phi_s + (cb + 8 + g) * 8 + tig * 2);
        float c0[4] = {0.f, 0.f, 0.f, 0.f};
        float c1[4] = {0.f, 0.f, 0.f, 0.f};
        mma_16n8k8(c0, tA0, tA1, bA);
        mma_16n8k8(c1, tA0, tA1, bB);

        float e00 = ex2f(c0[0] - m0), e01 = ex2f(c0[1] - m0);
        float e02 = ex2f(c0[2] - m1), e03 = ex2f(c0[3] - m1);
        float e10 = ex2f(c1[0] - m0), e11 = ex2f(c1[1] - m0);
        float e12 = ex2f(c1[2] - m1), e13 = ex2f(c1[3] - m1);
        l0 += e00 + e01 + e10 + e11;
        l1 += e02 + e03 + e12 + e13;
        u32 pA0 = f16x2_of(e00, e01);
        u32 pA1 = f16x2_of(e02, e03);
        u32 pA2 = f16x2_of(e10, e11);
        u32 pA3 = f16x2_of(e12, e13);

        const char* gbase = smem + G_OFF + (cb + tig * 2) * 2;
#pragma unroll
        for (int nt = 0; nt < 4; nt++) {
            int oc = nt * 8 + g;
            u32 b0 = *(const u32*)(gbase + oc * GROW);
            u32 b1 = *(const u32*)(gbase + oc * GROW + 16);
            mma_16n8k16(o[nt], pA0, pA1, pA2, pA3, b0, b1);
        }
    }

    // --- reduce l across quad, stash O + l ---
    l0 += __shfl_xor_sync(0xFFFFFFFF, l0, 1);
    l0 += __shfl_xor_sync(0xFFFFFFFF, l0, 2);
    l1 += __shfl_xor_sync(0xFFFFFFFF, l1, 1);
    l1 += __shfl_xor_sync(0xFFFFFFFF, l1, 2);
    if (tig == 0) {
        l_s[w * 16 + g] = l0;
        l_s[w * 16 + g + 8] = l1;
    }
#pragma unroll
    for (int nt = 0; nt < 4; nt++) {
        int col = nt * 8 + tig * 2;
        *(float2*)(o_s + (w * 16 + g) * OROW + col)     = make_float2(o[nt][0], o[nt][1]);
        *(float2*)(o_s + (w * 16 + g + 8) * OROW + col) = make_float2(o[nt][2], o[nt][3]);
    }
    __syncthreads();

    // --- epilogue: out = (gamma/l) * (w_o @ o) + x, 2 threads per query ---
    int q = tid & 127, half = tid >> 7;
    float n0 = gamma_p[0] / l_s[q];
    ull o2[16];
    {
        const float* op = o_s + q * OROW;
#pragma unroll
        for (int j = 0; j < 16; j++)
            o2[j] = pack2(op[2 * j], op[2 * j + 1]);
    }
    int sidx = q0b + q;
    const float* xr = x + (size_t)b * CHAN * S + sidx;
    float* orow = out + (size_t)b * CHAN * S + sidx;
    for (int co = half * 32; co < half * 32 + 32; co++) {
        const double2* wr = (const double2*)(wo_s + co * 32);
        ull acc = 0ull;
#pragma unroll
        for (int j = 0; j < 8; j++) {
            double2 wv = wr[j];
            acc = ffma2(d2u(wv.x), o2[2 * j], acc);
            acc = ffma2(d2u(wv.y), o2[2 * j + 1], acc);
        }
        float lo, hi;
        unpack2(acc, lo, hi);
        orow[(size_t)co * S] = n0 * (lo + hi) + xr[(size_t)co * S];
    }
}

// ---------------------------------------------------------------------------
extern "C" void kernel_launch(void* const* d_in, const int* in_sizes, int n_in,
                              void* d_out, int out_size)
{
    const float* x       = (const float*)d_in[0];
    const float* w_theta = (const float*)d_in[1];
    const float* w_phi   = (const float*)d_in[2];
    const float* w_g     = (const float*)d_in[3];
    const float* w_o     = (const float*)d_in[4];
    const float* gamma   = (const float*)d_in[5];
    float* out = (float*)d_out;

    convpool_kernel<<<640, 256>>>(x, w_phi, w_g);
    theta_kernel<<<256, 256>>>(x, w_theta);

    cudaFuncSetAttribute(attn_hmma, cudaFuncAttributeMaxDynamicSharedMemorySize, SMEM_REQ);
    attn_hmma<<<512, 256, SMEM_REQ>>>(x, w_o, gamma, out);
}

// round 10
// speedup vs baseline: 2.9237x; 1.1078x over previous
#include <cuda_runtime.h>
#include <cuda_fp16.h>

typedef unsigned long long ull;
typedef unsigned int u32;

#define BATCH 16
#define CHAN  64
#define S     4096
#define S4    1024

__device__ __align__(16) __half g_phi16[BATCH * S4 * 8];  // [b][t][8]
__device__ __align__(16) __half g_g16[BATCH * 32 * S4];   // [b][oc][t]
__device__ __align__(16) __half g_th16[BATCH * S * 8];    // [b][s][8] *log2e

// ---------------- helpers ----------------
__device__ __forceinline__ float ex2f(float a) {
    float r; asm("ex2.approx.ftz.f32 %0, %1;" : "=f"(r) : "f"(a)); return r;
}
__device__ __forceinline__ u32 f16x2_of(float lo, float hi) {
    u32 r; asm("cvt.rn.f16x2.f32 %0, %1, %2;" : "=r"(r) : "f"(hi), "f"(lo)); return r;
}
__device__ __forceinline__ u32 h2u(__half2 h) { return *reinterpret_cast<u32*>(&h); }
__device__ __forceinline__ ull pack2(float a, float b) {
    ull r; asm("mov.b64 %0, {%1, %2};" : "=l"(r) : "f"(a), "f"(b)); return r;
}
__device__ __forceinline__ void unpack2(ull v, float& a, float& b) {
    asm("mov.b64 {%0, %1}, %2;" : "=f"(a), "=f"(b) : "l"(v));
}
__device__ __forceinline__ ull ffma2(ull a, ull b, ull c) {
    ull d; asm("fma.rn.f32x2 %0, %1, %2, %3;" : "=l"(d) : "l"(a), "l"(b), "l"(c)); return d;
}
__device__ __forceinline__ ull d2u(double d) { return __double_as_longlong(d); }

__device__ __forceinline__ void mma_16n8k8(float* c, u32 a0, u32 a1, u32 b0) {
    asm volatile("mma.sync.aligned.m16n8k8.row.col.f32.f16.f16.f32 "
        "{%0,%1,%2,%3}, {%4,%5}, {%6}, {%0,%1,%2,%3};"
        : "+f"(c[0]), "+f"(c[1]), "+f"(c[2]), "+f"(c[3])
        : "r"(a0), "r"(a1), "r"(b0));
}
__device__ __forceinline__ void mma_16n8k16(float* c, u32 a0, u32 a1, u32 a2, u32 a3,
                                            u32 b0, u32 b1) {
    asm volatile("mma.sync.aligned.m16n8k16.row.col.f32.f16.f16.f32 "
        "{%0,%1,%2,%3}, {%4,%5,%6,%7}, {%8,%9}, {%0,%1,%2,%3};"
        : "+f"(c[0]), "+f"(c[1]), "+f"(c[2]), "+f"(c[3])
        : "r"(a0), "r"(a1), "r"(a2), "r"(a3), "r"(b0), "r"(b1));
}

// prep kernel dynamic smem: xs [64*256 floats] = 65536 B, ws [48*64 ull] = 24576 B
#define PREP_XS_OFF 0
#define PREP_WS_OFF 65536
#define PREP_SMEM   90112

// ---------------------------------------------------------------------------
// Fused prep: 1x1 convs (theta 8, phi 8, g 32) + 2x2 maxpool for phi/g.
// Block = (batch, 4-pixel-row tile). x tile staged in smem ONCE; weights
// staged as duplicated f32x2 pairs (theta rows pre-multiplied by log2e).
// Thread = one 2x2 pooled window x 12 channels (warp-uniform channel group).
// ---------------------------------------------------------------------------
__global__ void __launch_bounds__(256, 2) prep_kernel(
    const float* __restrict__ x, const float* __restrict__ w_theta,
    const float* __restrict__ w_phi, const float* __restrict__ w_g)
{
    extern __shared__ char psm[];
    float* xs = (float*)(psm + PREP_XS_OFF);   // [c][4 rows][64 cols]
    ull*   ws = (ull*)(psm + PREP_WS_OFF);     // dup-packed weights

    const int tid = threadIdx.x;
    const int b   = blockIdx.x >> 4;
    const int rt  = blockIdx.x & 15;        // 4-pixel-row tile

    // --- stage x tile (coalesced: 256 contiguous floats per channel) ---
    {
        const float4* src = (const float4*)(x + (size_t)b * CHAN * S + rt * 256);
        for (int i = tid; i < 4096; i += 256) {
            int c = i >> 6, f = i & 63;
            ((float4*)xs)[i] = src[c * (S / 4) + f];
        }
    }
    // --- stage weights, duplicated into f32x2 pairs; theta rows * log2e ---
    for (int i = tid; i < 3072; i += 256) {
        int u = i >> 6, c = i & 63;
        float w;
        if (u < 8)        w = w_theta[u * 64 + c] * 1.4426950408889634f;
        else if (u < 16)  w = w_phi[(u - 8) * 64 + c];
        else              w = w_g[(u - 16) * 64 + c];
        ws[i] = pack2(w, w);
    }
    __syncthreads();

    const int pos = tid & 63, ogrp = tid >> 6;
    const int pr = pos >> 5, pc = pos & 31;       // pooled (row, col) in tile
    const int u0 = ogrp * 12;

    ull acc[12][2];
#pragma unroll
    for (int j = 0; j < 12; j++) acc[j][0] = acc[j][1] = 0ull;

    const float* xp = xs + (2 * pr) * 64 + 2 * pc;
    const ull* wp = ws + u0 * 64;
#pragma unroll 2
    for (int c = 0; c < CHAN; c++) {
        ull a0 = *(const ull*)(xp + c * 256);        // row 2pr, cols 2pc..2pc+1
        ull a1 = *(const ull*)(xp + c * 256 + 64);   // row 2pr+1
#pragma unroll
        for (int j = 0; j < 12; j++) {
            ull w = wp[j * 64 + c];
            acc[j][0] = ffma2(a0, w, acc[j][0]);
            acc[j][1] = ffma2(a1, w, acc[j][1]);
        }
    }

    // unpack: v[j][px], px = r*2+cc
    float v[12][4];
#pragma unroll
    for (int j = 0; j < 12; j++) {
        unpack2(acc[j][0], v[j][0], v[j][1]);
        unpack2(acc[j][1], v[j][2], v[j][3]);
    }

    const int t = (rt * 2 + pr) * 32 + pc;           // pooled index
    const int h0 = rt * 4 + 2 * pr, w0c = 2 * pc;    // pixel base

    if (ogrp == 0) {
        // theta (u 0..7): per-pixel uint4 of 8 halves
#pragma unroll
        for (int px = 0; px < 4; px++) {
            int s = (h0 + (px >> 1)) * 64 + w0c + (px & 1);
            uint4 o;
            o.x = f16x2_of(v[0][px], v[1][px]);
            o.y = f16x2_of(v[2][px], v[3][px]);
            o.z = f16x2_of(v[4][px], v[5][px]);
            o.w = f16x2_of(v[6][px], v[7][px]);
            *(uint4*)(g_th16 + (size_t)(b * S + s) * 8) = o;
        }
        // phi 0..3 (u 8..11): pooled max -> uint2
        float m[4];
#pragma unroll
        for (int j = 8; j < 12; j++)
            m[j - 8] = fmaxf(fmaxf(v[j][0], v[j][1]), fmaxf(v[j][2], v[j][3]));
        uint2 o;
        o.x = f16x2_of(m[0], m[1]);
        o.y = f16x2_of(m[2], m[3]);
        *(uint2*)(g_phi16 + (size_t)(b * S4 + t) * 8) = o;
    } else if (ogrp == 1) {
        // phi 4..7 (u 12..15)
        float m[4];
#pragma unroll
        for (int j = 0; j < 4; j++)
            m[j] = fmaxf(fmaxf(v[j][0], v[j][1]), fmaxf(v[j][2], v[j][3]));
        uint2 o;
        o.x = f16x2_of(m[0], m[1]);
        o.y = f16x2_of(m[2], m[3]);
        *(uint2*)(g_phi16 + (size_t)(b * S4 + t) * 8 + 4) = o;
        // g 0..7 (u 16..23)
#pragma unroll
        for (int j = 4; j < 12; j++) {
            float mm = fmaxf(fmaxf(v[j][0], v[j][1]), fmaxf(v[j][2], v[j][3]));
            g_g16[((size_t)b * 32 + (j - 4)) * S4 + t] = __float2half(mm);
        }
    } else {
        // g 8..19 (ogrp2) / g 20..31 (ogrp3)
        int oc0 = (ogrp == 2) ? 8 : 20;
#pragma unroll
        for (int j = 0; j < 12; j++) {
            float mm = fmaxf(fmaxf(v[j][0], v[j][1]), fmaxf(v[j][2], v[j][3]));
            g_g16[((size_t)b * 32 + oc0 + j) * S4 + t] = __float2half(mm);
        }
    }
}

// smem byte offsets for attention kernel (dynamic)
#define PHI_OFF 0
#define G_OFF   16384
#define GROW    2064
#define O_OFF   82432
#define OROW    34
#define L_OFF   99840
#define WO_OFF  100352
#define SMEM_REQ 108544

// ---------------------------------------------------------------------------
// Attention: warp-level HMMA flash, two-pass (per-query max, then exp+PV).
// ---------------------------------------------------------------------------
__global__ void __launch_bounds__(256, 2) attn_hmma(
    const float* __restrict__ x, const float* __restrict__ w_o,
    const float* __restrict__ gamma_p, float* __restrict__ out)
{
    extern __shared__ char smem[];
    __half* phi_s = (__half*)(smem + PHI_OFF);
    float*  o_s   = (float*)(smem + O_OFF);
    float*  l_s   = (float*)(smem + L_OFF);
    float*  wo_s  = (float*)(smem + WO_OFF);

    const int tid = threadIdx.x;
    const int w   = tid >> 5;
    const int lane = tid & 31;
    const int g   = lane >> 2;
    const int tig = lane & 3;
    const int b   = blockIdx.x >> 5;
    const int q0b = (blockIdx.x & 31) * 128;
    const int qw  = q0b + w * 16;

    {
        const uint4* src = (const uint4*)(g_phi16 + (size_t)b * S4 * 8);
        uint4* dst = (uint4*)phi_s;
        for (int i = tid; i < 1024; i += 256) dst[i] = src[i];
    }
    for (int i = tid; i < 4096; i += 256) {
        int oc = i >> 7, j = i & 127;
        uint4 v = *(const uint4*)(g_g16 + ((size_t)b * 32 + oc) * S4 + j * 8);
        *(uint4*)(smem + G_OFF + oc * GROW + j * 16) = v;
    }
    for (int i = tid; i < 512; i += 256)
        ((float4*)wo_s)[i] = ((const float4*)w_o)[i];
    __syncthreads();

    u32 tA0 = *(const u32*)(g_th16 + (size_t)(b * S + qw + g) * 8 + tig * 2);
    u32 tA1 = *(const u32*)(g_th16 + (size_t)(b * S + qw + 8 + g) * 8 + tig * 2);

    // pass 1: per-query row max
    float m0 = -1e30f, m1 = -1e30f;
#pragma unroll 4
    for (int cb = 0; cb < S4; cb += 16) {
        u32 bA = *(const u32*)(phi_s + (cb + g) * 8 + tig * 2);
        u32 bB = *(const u32*)(phi_s + (cb + 8 + g) * 8 + tig * 2);
        float c0[4] = {0.f, 0.f, 0.f, 0.f};
        float c1[4] = {0.f, 0.f, 0.f, 0.f};
        mma_16n8k8(c0, tA0, tA1, bA);
        mma_16n8k8(c1, tA0, tA1, bB);
        m0 = fmaxf(m0, fmaxf(fmaxf(c0[0], c0[1]), fmaxf(c1[0], c1[1])));
        m1 = fmaxf(m1, fmaxf(fmaxf(c0[2], c0[3]), fmaxf(c1[2], c1[3])));
    }
    m0 = fmaxf(m0, __shfl_xor_sync(0xFFFFFFFF, m0, 1));
    m0 = fmaxf(m0, __shfl_xor_sync(0xFFFFFFFF, m0, 2));
    m1 = fmaxf(m1, __shfl_xor_sync(0xFFFFFFFF, m1, 1));
    m1 = fmaxf(m1, __shfl_xor_sync(0xFFFFFFFF, m1, 2));

    // pass 2: p = exp2(s - m), accumulate l and O
    float o[4][4];
#pragma unroll
    for (int nt = 0; nt < 4; nt++)
#pragma unroll
        for (int j = 0; j < 4; j++) o[nt][j] = 0.f;
    float l0 = 0.f, l1 = 0.f;

#pragma unroll 2
    for (int cb = 0; cb < S4; cb += 16) {
        u32 bA = *(const u32*)(phi_s + (cb + g) * 8 + tig * 2);
        u32 bB = *(const u32*)(phi_s + (cb + 8 + g) * 8 + tig * 2);
        float c0[4] = {0.f, 0.f, 0.f, 0.f};
        float c1[4] = {0.f, 0.f, 0.f, 0.f};
        mma_16n8k8(c0, tA0, tA1, bA);
        mma_16n8k8(c1, tA0, tA1, bB);

        float e00 = ex2f(c0[0] - m0), e01 = ex2f(c0[1] - m0);
        float e02 = ex2f(c0[2] - m1), e03 = ex2f(c0[3] - m1);
        float e10 = ex2f(c1[0] - m0), e11 = ex2f(c1[1] - m0);
        float e12 = ex2f(c1[2] - m1), e13 = ex2f(c1[3] - m1);
        l0 += e00 + e01 + e10 + e11;
        l1 += e02 + e03 + e12 + e13;
        u32 pA0 = f16x2_of(e00, e01);
        u32 pA1 = f16x2_of(e02, e03);
        u32 pA2 = f16x2_of(e10, e11);
        u32 pA3 = f16x2_of(e12, e13);

        const char* gbase = smem + G_OFF + (cb + tig * 2) * 2;
#pragma unroll
        for (int nt = 0; nt < 4; nt++) {
            int oc = nt * 8 + g;
            u32 b0 = *(const u32*)(gbase + oc * GROW);
            u32 b1 = *(const u32*)(gbase + oc * GROW + 16);
            mma_16n8k16(o[nt], pA0, pA1, pA2, pA3, b0, b1);
        }
    }

    l0 += __shfl_xor_sync(0xFFFFFFFF, l0, 1);
    l0 += __shfl_xor_sync(0xFFFFFFFF, l0, 2);
    l1 += __shfl_xor_sync(0xFFFFFFFF, l1, 1);
    l1 += __shfl_xor_sync(0xFFFFFFFF, l1, 2);
    if (tig == 0) {
        l_s[w * 16 + g] = l0;
        l_s[w * 16 + g + 8] = l1;
    }
#pragma unroll
    for (int nt = 0; nt < 4; nt++) {
        int col = nt * 8 + tig * 2;
        *(float2*)(o_s + (w * 16 + g) * OROW + col)     = make_float2(o[nt][0], o[nt][1]);
        *(float2*)(o_s + (w * 16 + g + 8) * OROW + col) = make_float2(o[nt][2], o[nt][3]);
    }
    __syncthreads();

    int q = tid & 127, half = tid >> 7;
    float n0 = gamma_p[0] / l_s[q];
    ull o2[16];
    {
        const float* op = o_s + q * OROW;
#pragma unroll
        for (int j = 0; j < 16; j++)
            o2[j] = pack2(op[2 * j], op[2 * j + 1]);
    }
    int sidx = q0b + q;
    const float* xr = x + (size_t)b * CHAN * S + sidx;
    float* orow = out + (size_t)b * CHAN * S + sidx;
    for (int co = half * 32; co < half * 32 + 32; co++) {
        const double2* wr = (const double2*)(wo_s + co * 32);
        ull acc = 0ull;
#pragma unroll
        for (int j = 0; j < 8; j++) {
            double2 wv = wr[j];
            acc = ffma2(d2u(wv.x), o2[2 * j], acc);
            acc = ffma2(d2u(wv.y), o2[2 * j + 1], acc);
        }
        float lo, hi;
        unpack2(acc, lo, hi);
        orow[(size_t)co * S] = n0 * (lo + hi) + xr[(size_t)co * S];
    }
}

// ---------------------------------------------------------------------------
extern "C" void kernel_launch(void* const* d_in, const int* in_sizes, int n_in,
                              void* d_out, int out_size)
{
    const float* x       = (const float*)d_in[0];
    const float* w_theta = (const float*)d_in[1];
    const float* w_phi   = (const float*)d_in[2];
    const float* w_g     = (const float*)d_in[3];
    const float* w_o     = (const float*)d_in[4];
    const float* gamma   = (const float*)d_in[5];
    float* out = (float*)d_out;

    cudaFuncSetAttribute(prep_kernel, cudaFuncAttributeMaxDynamicSharedMemorySize, PREP_SMEM);
    prep_kernel<<<256, 256, PREP_SMEM>>>(x, w_theta, w_phi, w_g);

    cudaFuncSetAttribute(attn_hmma, cudaFuncAttributeMaxDynamicSharedMemorySize, SMEM_REQ);
    attn_hmma<<<512, 256, SMEM_REQ>>>(x, w_o, gamma, out);
}

// round 11
// speedup vs baseline: 3.0708x; 1.0503x over previous
#include <cuda_runtime.h>
#include <cuda_fp16.h>

typedef unsigned long long ull;
typedef unsigned int u32;

#define BATCH 16
#define CHAN  64
#define S     4096
#define S4    1024

__device__ __align__(16) __half g_phi16[BATCH * S4 * 8];  // [b][t][8]
__device__ __align__(16) __half g_g16[BATCH * 32 * S4];   // [b][oc][t]
__device__ __align__(16) __half g_th16[BATCH * S * 8];    // [b][s][8] *log2e

// ---------------- helpers ----------------
__device__ __forceinline__ float ex2f(float a) {
    float r; asm("ex2.approx.ftz.f32 %0, %1;" : "=f"(r) : "f"(a)); return r;
}
__device__ __forceinline__ u32 f16x2_of(float lo, float hi) {
    u32 r; asm("cvt.rn.f16x2.f32 %0, %1, %2;" : "=r"(r) : "f"(hi), "f"(lo)); return r;
}
__device__ __forceinline__ u32 h2u(__half2 h) { return *reinterpret_cast<u32*>(&h); }
__device__ __forceinline__ ull pack2(float a, float b) {
    ull r; asm("mov.b64 %0, {%1, %2};" : "=l"(r) : "f"(a), "f"(b)); return r;
}
__device__ __forceinline__ void unpack2(ull v, float& a, float& b) {
    asm("mov.b64 {%0, %1}, %2;" : "=f"(a), "=f"(b) : "l"(v));
}
__device__ __forceinline__ ull ffma2(ull a, ull b, ull c) {
    ull d; asm("fma.rn.f32x2 %0, %1, %2, %3;" : "=l"(d) : "l"(a), "l"(b), "l"(c)); return d;
}
__device__ __forceinline__ ull d2u(double d) { return __double_as_longlong(d); }

__device__ __forceinline__ void mma_16n8k8(float* c, u32 a0, u32 a1, u32 b0) {
    asm volatile("mma.sync.aligned.m16n8k8.row.col.f32.f16.f16.f32 "
        "{%0,%1,%2,%3}, {%4,%5}, {%6}, {%0,%1,%2,%3};"
        : "+f"(c[0]), "+f"(c[1]), "+f"(c[2]), "+f"(c[3])
        : "r"(a0), "r"(a1), "r"(b0));
}
__device__ __forceinline__ void mma_16n8k16(float* c, u32 a0, u32 a1, u32 a2, u32 a3,
                                            u32 b0, u32 b1) {
    asm volatile("mma.sync.aligned.m16n8k16.row.col.f32.f16.f16.f32 "
        "{%0,%1,%2,%3}, {%4,%5,%6,%7}, {%8,%9}, {%0,%1,%2,%3};"
        : "+f"(c[0]), "+f"(c[1]), "+f"(c[2]), "+f"(c[3])
        : "r"(a0), "r"(a1), "r"(a2), "r"(a3), "r"(b0), "r"(b1));
}

// prep kernel dynamic smem
#define PREP_XS_OFF 0
#define PREP_WS_OFF 65536
#define PREP_SMEM   90112

// ---------------------------------------------------------------------------
// Fused prep: 1x1 convs (theta 8, phi 8, g 32) + 2x2 maxpool for phi/g.
// ---------------------------------------------------------------------------
__global__ void __launch_bounds__(256, 2) prep_kernel(
    const float* __restrict__ x, const float* __restrict__ w_theta,
    const float* __restrict__ w_phi, const float* __restrict__ w_g)
{
    extern __shared__ char psm[];
    float* xs = (float*)(psm + PREP_XS_OFF);   // [c][4 rows][64 cols]
    ull*   ws = (ull*)(psm + PREP_WS_OFF);     // dup-packed weights

    const int tid = threadIdx.x;
    const int b   = blockIdx.x >> 4;
    const int rt  = blockIdx.x & 15;

    {
        const float4* src = (const float4*)(x + (size_t)b * CHAN * S + rt * 256);
        for (int i = tid; i < 4096; i += 256) {
            int c = i >> 6, f = i & 63;
            ((float4*)xs)[i] = src[c * (S / 4) + f];
        }
    }
    for (int i = tid; i < 3072; i += 256) {
        int u = i >> 6, c = i & 63;
        float w;
        if (u < 8)        w = w_theta[u * 64 + c] * 1.4426950408889634f;
        else if (u < 16)  w = w_phi[(u - 8) * 64 + c];
        else              w = w_g[(u - 16) * 64 + c];
        ws[i] = pack2(w, w);
    }
    __syncthreads();

    const int pos = tid & 63, ogrp = tid >> 6;
    const int pr = pos >> 5, pc = pos & 31;
    const int u0 = ogrp * 12;

    ull acc[12][2];
#pragma unroll
    for (int j = 0; j < 12; j++) acc[j][0] = acc[j][1] = 0ull;

    const float* xp = xs + (2 * pr) * 64 + 2 * pc;
    const ull* wp = ws + u0 * 64;
#pragma unroll 2
    for (int c = 0; c < CHAN; c++) {
        ull a0 = *(const ull*)(xp + c * 256);
        ull a1 = *(const ull*)(xp + c * 256 + 64);
#pragma unroll
        for (int j = 0; j < 12; j++) {
            ull w = wp[j * 64 + c];
            acc[j][0] = ffma2(a0, w, acc[j][0]);
            acc[j][1] = ffma2(a1, w, acc[j][1]);
        }
    }

    float v[12][4];
#pragma unroll
    for (int j = 0; j < 12; j++) {
        unpack2(acc[j][0], v[j][0], v[j][1]);
        unpack2(acc[j][1], v[j][2], v[j][3]);
    }

    const int t = (rt * 2 + pr) * 32 + pc;
    const int h0 = rt * 4 + 2 * pr, w0c = 2 * pc;

    if (ogrp == 0) {
#pragma unroll
        for (int px = 0; px < 4; px++) {
            int s = (h0 + (px >> 1)) * 64 + w0c + (px & 1);
            uint4 o;
            o.x = f16x2_of(v[0][px], v[1][px]);
            o.y = f16x2_of(v[2][px], v[3][px]);
            o.z = f16x2_of(v[4][px], v[5][px]);
            o.w = f16x2_of(v[6][px], v[7][px]);
            *(uint4*)(g_th16 + (size_t)(b * S + s) * 8) = o;
        }
        float m[4];
#pragma unroll
        for (int j = 8; j < 12; j++)
            m[j - 8] = fmaxf(fmaxf(v[j][0], v[j][1]), fmaxf(v[j][2], v[j][3]));
        uint2 o;
        o.x = f16x2_of(m[0], m[1]);
        o.y = f16x2_of(m[2], m[3]);
        *(uint2*)(g_phi16 + (size_t)(b * S4 + t) * 8) = o;
    } else if (ogrp == 1) {
        float m[4];
#pragma unroll
        for (int j = 0; j < 4; j++)
            m[j] = fmaxf(fmaxf(v[j][0], v[j][1]), fmaxf(v[j][2], v[j][3]));
        uint2 o;
        o.x = f16x2_of(m[0], m[1]);
        o.y = f16x2_of(m[2], m[3]);
        *(uint2*)(g_phi16 + (size_t)(b * S4 + t) * 8 + 4) = o;
#pragma unroll
        for (int j = 4; j < 12; j++) {
            float mm = fmaxf(fmaxf(v[j][0], v[j][1]), fmaxf(v[j][2], v[j][3]));
            g_g16[((size_t)b * 32 + (j - 4)) * S4 + t] = __float2half(mm);
        }
    } else {
        int oc0 = (ogrp == 2) ? 8 : 20;
#pragma unroll
        for (int j = 0; j < 12; j++) {
            float mm = fmaxf(fmaxf(v[j][0], v[j][1]), fmaxf(v[j][2], v[j][3]));
            g_g16[((size_t)b * 32 + oc0 + j) * S4 + t] = __float2half(mm);
        }
    }
}

// attention smem offsets
#define PHI_OFF 0
#define G_OFF   16384
#define GROW    2064
#define O_OFF   82432
#define OROW    34
#define L_OFF   99840
#define WO_OFF  100352
#define SMEM_REQ 108544

// ---------------------------------------------------------------------------
// Attention: warp-level HMMA flash. Pass 1 samples 1 chunk in 4 for the
// row max (fp16 holds up to 2^16, so a <=16-log2 max underestimate is safe;
// +2 margin cancels in o/l). Pass 2: p = exp2(s - m), accumulate l and O.
// ---------------------------------------------------------------------------
__global__ void __launch_bounds__(256, 2) attn_hmma(
    const float* __restrict__ x, const float* __restrict__ w_o,
    const float* __restrict__ gamma_p, float* __restrict__ out)
{
    extern __shared__ char smem[];
    __half* phi_s = (__half*)(smem + PHI_OFF);
    float*  o_s   = (float*)(smem + O_OFF);
    float*  l_s   = (float*)(smem + L_OFF);
    float*  wo_s  = (float*)(smem + WO_OFF);

    const int tid = threadIdx.x;
    const int w   = tid >> 5;
    const int lane = tid & 31;
    const int g   = lane >> 2;
    const int tig = lane & 3;
    const int b   = blockIdx.x >> 5;
    const int q0b = (blockIdx.x & 31) * 128;
    const int qw  = q0b + w * 16;

    {
        const uint4* src = (const uint4*)(g_phi16 + (size_t)b * S4 * 8);
        uint4* dst = (uint4*)phi_s;
        for (int i = tid; i < 1024; i += 256) dst[i] = src[i];
    }
    for (int i = tid; i < 4096; i += 256) {
        int oc = i >> 7, j = i & 127;
        uint4 v = *(const uint4*)(g_g16 + ((size_t)b * 32 + oc) * S4 + j * 8);
        *(uint4*)(smem + G_OFF + oc * GROW + j * 16) = v;
    }
    for (int i = tid; i < 512; i += 256)
        ((float4*)wo_s)[i] = ((const float4*)w_o)[i];
    __syncthreads();

    u32 tA0 = *(const u32*)(g_th16 + (size_t)(b * S + qw + g) * 8 + tig * 2);
    u32 tA1 = *(const u32*)(g_th16 + (size_t)(b * S + qw + 8 + g) * 8 + tig * 2);

    // pass 1 (subsampled, stride-4 chunks): approximate per-query row max
    float m0 = -1e30f, m1 = -1e30f;
#pragma unroll 4
    for (int cb = 0; cb < S4; cb += 64) {
        u32 bA = *(const u32*)(phi_s + (cb + g) * 8 + tig * 2);
        u32 bB = *(const u32*)(phi_s + (cb + 8 + g) * 8 + tig * 2);
        float c0[4] = {0.f, 0.f, 0.f, 0.f};
        float c1[4] = {0.f, 0.f, 0.f, 0.f};
        mma_16n8k8(c0, tA0, tA1, bA);
        mma_16n8k8(c1, tA0, tA1, bB);
        m0 = fmaxf(m0, fmaxf(fmaxf(c0[0], c0[1]), fmaxf(c1[0], c1[1])));
        m1 = fmaxf(m1, fmaxf(fmaxf(c0[2], c0[3]), fmaxf(c1[2], c1[3])));
    }
    m0 = fmaxf(m0, __shfl_xor_sync(0xFFFFFFFF, m0, 1));
    m0 = fmaxf(m0, __shfl_xor_sync(0xFFFFFFFF, m0, 2)) + 2.0f;
    m1 = fmaxf(m1, __shfl_xor_sync(0xFFFFFFFF, m1, 1));
    m1 = fmaxf(m1, __shfl_xor_sync(0xFFFFFFFF, m1, 2)) + 2.0f;

    // pass 2: p = exp2(s - m), accumulate l and O
    float o[4][4];
#pragma unroll
    for (int nt = 0; nt < 4; nt++)
#pragma unroll
        for (int j = 0; j < 4; j++) o[nt][j] = 0.f;
    float l0 = 0.f, l1 = 0.f;

#pragma unroll 2
    for (int cb = 0; cb < S4; cb += 16) {
        u32 bA = *(const u32*)(phi_s + (cb + g) * 8 + tig * 2);
        u32 bB = *(const u32*)(phi_s + (cb + 8 + g) * 8 + tig * 2);
        float c0[4] = {0.f, 0.f, 0.f, 0.f};
        float c1[4] = {0.f, 0.f, 0.f, 0.f};
        mma_16n8k8(c0, tA0, tA1, bA);
        mma_16n8k8(c1, tA0, tA1, bB);

        float e00 = ex2f(c0[0] - m0), e01 = ex2f(c0[1] - m0);
        float e02 = ex2f(c0[2] - m1), e03 = ex2f(c0[3] - m1);
        float e10 = ex2f(c1[0] - m0), e11 = ex2f(c1[1] - m0);
        float e12 = ex2f(c1[2] - m1), e13 = ex2f(c1[3] - m1);
        l0 += e00 + e01 + e10 + e11;
        l1 += e02 + e03 + e12 + e13;
        u32 pA0 = f16x2_of(e00, e01);
        u32 pA1 = f16x2_of(e02, e03);
        u32 pA2 = f16x2_of(e10, e11);
        u32 pA3 = f16x2_of(e12, e13);

        const char* gbase = smem + G_OFF + (cb + tig * 2) * 2;
#pragma unroll
        for (int nt = 0; nt < 4; nt++) {
            int oc = nt * 8 + g;
            u32 b0 = *(const u32*)(gbase + oc * GROW);
            u32 b1 = *(const u32*)(gbase + oc * GROW + 16);
            mma_16n8k16(o[nt], pA0, pA1, pA2, pA3, b0, b1);
        }
    }

    l0 += __shfl_xor_sync(0xFFFFFFFF, l0, 1);
    l0 += __shfl_xor_sync(0xFFFFFFFF, l0, 2);
    l1 += __shfl_xor_sync(0xFFFFFFFF, l1, 1);
    l1 += __shfl_xor_sync(0xFFFFFFFF, l1, 2);
    if (tig == 0) {
        l_s[w * 16 + g] = l0;
        l_s[w * 16 + g + 8] = l1;
    }
#pragma unroll
    for (int nt = 0; nt < 4; nt++) {
        int col = nt * 8 + tig * 2;
        *(float2*)(o_s + (w * 16 + g) * OROW + col)     = make_float2(o[nt][0], o[nt][1]);
        *(float2*)(o_s + (w * 16 + g + 8) * OROW + col) = make_float2(o[nt][2], o[nt][3]);
    }
    __syncthreads();

    int q = tid & 127, half = tid >> 7;
    float n0 = gamma_p[0] / l_s[q];
    ull o2[16];
    {
        const float* op = o_s + q * OROW;
#pragma unroll
        for (int j = 0; j < 16; j++)
            o2[j] = pack2(op[2 * j], op[2 * j + 1]);
    }
    int sidx = q0b + q;
    const float* xr = x + (size_t)b * CHAN * S + sidx;
    float* orow = out + (size_t)b * CHAN * S + sidx;
    for (int co = half * 32; co < half * 32 + 32; co++) {
        const double2* wr = (const double2*)(wo_s + co * 32);
        ull acc = 0ull;
#pragma unroll
        for (int j = 0; j < 8; j++) {
            double2 wv = wr[j];
            acc = ffma2(d2u(wv.x), o2[2 * j], acc);
            acc = ffma2(d2u(wv.y), o2[2 * j + 1], acc);
        }
        float lo, hi;
        unpack2(acc, lo, hi);
        orow[(size_t)co * S] = n0 * (lo + hi) + xr[(size_t)co * S];
    }
}

// ---------------------------------------------------------------------------
extern "C" void kernel_launch(void* const* d_in, const int* in_sizes, int n_in,
                              void* d_out, int out_size)
{
    const float* x       = (const float*)d_in[0];
    const float* w_theta = (const float*)d_in[1];
    const float* w_phi   = (const float*)d_in[2];
    const float* w_g     = (const float*)d_in[3];
    const float* w_o     = (const float*)d_in[4];
    const float* gamma   = (const float*)d_in[5];
    float* out = (float*)d_out;

    cudaFuncSetAttribute(prep_kernel, cudaFuncAttributeMaxDynamicSharedMemorySize, PREP_SMEM);
    prep_kernel<<<256, 256, PREP_SMEM>>>(x, w_theta, w_phi, w_g);

    cudaFuncSetAttribute(attn_hmma, cudaFuncAttributeMaxDynamicSharedMemorySize, SMEM_REQ);
    attn_hmma<<<512, 256, SMEM_REQ>>>(x, w_o, gamma, out);
}

// round 12
// speedup vs baseline: 3.3081x; 1.0773x over previous
#include <cuda_runtime.h>
#include <cuda_fp16.h>

typedef unsigned long long ull;
typedef unsigned int u32;

#define BATCH 16
#define CHAN  64
#define S     4096
#define S4    1024

__device__ __align__(16) __half g_phi16[BATCH * S4 * 8];  // [b][t][8]
__device__ __align__(16) __half g_g16[BATCH * 32 * S4];   // [b][oc][t]
__device__ __align__(16) __half g_th16[BATCH * S * 8];    // [b][s][8] *log2e

// ---------------- helpers ----------------
__device__ __forceinline__ float ex2f(float a) {
    float r; asm("ex2.approx.ftz.f32 %0, %1;" : "=f"(r) : "f"(a)); return r;
}
__device__ __forceinline__ u32 f16x2_of(float lo, float hi) {
    u32 r; asm("cvt.rn.f16x2.f32 %0, %1, %2;" : "=r"(r) : "f"(hi), "f"(lo)); return r;
}
__device__ __forceinline__ u32 h2u(__half2 h) { return *reinterpret_cast<u32*>(&h); }
__device__ __forceinline__ ull pack2(float a, float b) {
    ull r; asm("mov.b64 %0, {%1, %2};" : "=l"(r) : "f"(a), "f"(b)); return r;
}
__device__ __forceinline__ void unpack2(ull v, float& a, float& b) {
    asm("mov.b64 {%0, %1}, %2;" : "=f"(a), "=f"(b) : "l"(v));
}
__device__ __forceinline__ ull ffma2(ull a, ull b, ull c) {
    ull d; asm("fma.rn.f32x2 %0, %1, %2, %3;" : "=l"(d) : "l"(a), "l"(b), "l"(c)); return d;
}
__device__ __forceinline__ ull d2u(double d) { return __double_as_longlong(d); }

__device__ __forceinline__ void mma_16n8k8(float* c, u32 a0, u32 a1, u32 b0) {
    asm volatile("mma.sync.aligned.m16n8k8.row.col.f32.f16.f16.f32 "
        "{%0,%1,%2,%3}, {%4,%5}, {%6}, {%0,%1,%2,%3};"
        : "+f"(c[0]), "+f"(c[1]), "+f"(c[2]), "+f"(c[3])
        : "r"(a0), "r"(a1), "r"(b0));
}
__device__ __forceinline__ void mma_16n8k16(float* c, u32 a0, u32 a1, u32 a2, u32 a3,
                                            u32 b0, u32 b1) {
    asm volatile("mma.sync.aligned.m16n8k16.row.col.f32.f16.f16.f32 "
        "{%0,%1,%2,%3}, {%4,%5,%6,%7}, {%8,%9}, {%0,%1,%2,%3};"
        : "+f"(c[0]), "+f"(c[1]), "+f"(c[2]), "+f"(c[3])
        : "r"(a0), "r"(a1), "r"(a2), "r"(a3), "r"(b0), "r"(b1));
}

// prep kernel dynamic smem
#define PREP_XS_OFF 0
#define PREP_WS_OFF 65536
#define PREP_SMEM   90112

// ---------------------------------------------------------------------------
// Fused prep: 1x1 convs (theta 8, phi 8, g 32) + 2x2 maxpool for phi/g.
// ---------------------------------------------------------------------------
__global__ void __launch_bounds__(256, 2) prep_kernel(
    const float* __restrict__ x, const float* __restrict__ w_theta,
    const float* __restrict__ w_phi, const float* __restrict__ w_g)
{
    extern __shared__ char psm[];
    float* xs = (float*)(psm + PREP_XS_OFF);
    ull*   ws = (ull*)(psm + PREP_WS_OFF);

    const int tid = threadIdx.x;
    const int b   = blockIdx.x >> 4;
    const int rt  = blockIdx.x & 15;

    {
        const float4* src = (const float4*)(x + (size_t)b * CHAN * S + rt * 256);
        for (int i = tid; i < 4096; i += 256) {
            int c = i >> 6, f = i & 63;
            ((float4*)xs)[i] = src[c * (S / 4) + f];
        }
    }
    for (int i = tid; i < 3072; i += 256) {
        int u = i >> 6, c = i & 63;
        float w;
        if (u < 8)        w = w_theta[u * 64 + c] * 1.4426950408889634f;
        else if (u < 16)  w = w_phi[(u - 8) * 64 + c];
        else              w = w_g[(u - 16) * 64 + c];
        ws[i] = pack2(w, w);
    }
    __syncthreads();

    const int pos = tid & 63, ogrp = tid >> 6;
    const int pr = pos >> 5, pc = pos & 31;
    const int u0 = ogrp * 12;

    ull acc[12][2];
#pragma unroll
    for (int j = 0; j < 12; j++) acc[j][0] = acc[j][1] = 0ull;

    const float* xp = xs + (2 * pr) * 64 + 2 * pc;
    const ull* wp = ws + u0 * 64;
#pragma unroll 2
    for (int c = 0; c < CHAN; c++) {
        ull a0 = *(const ull*)(xp + c * 256);
        ull a1 = *(const ull*)(xp + c * 256 + 64);
#pragma unroll
        for (int j = 0; j < 12; j++) {
            ull w = wp[j * 64 + c];
            acc[j][0] = ffma2(a0, w, acc[j][0]);
            acc[j][1] = ffma2(a1, w, acc[j][1]);
        }
    }

    float v[12][4];
#pragma unroll
    for (int j = 0; j < 12; j++) {
        unpack2(acc[j][0], v[j][0], v[j][1]);
        unpack2(acc[j][1], v[j][2], v[j][3]);
    }

    const int t = (rt * 2 + pr) * 32 + pc;
    const int h0 = rt * 4 + 2 * pr, w0c = 2 * pc;

    if (ogrp == 0) {
#pragma unroll
        for (int px = 0; px < 4; px++) {
            int s = (h0 + (px >> 1)) * 64 + w0c + (px & 1);
            uint4 o;
            o.x = f16x2_of(v[0][px], v[1][px]);
            o.y = f16x2_of(v[2][px], v[3][px]);
            o.z = f16x2_of(v[4][px], v[5][px]);
            o.w = f16x2_of(v[6][px], v[7][px]);
            *(uint4*)(g_th16 + (size_t)(b * S + s) * 8) = o;
        }
        float m[4];
#pragma unroll
        for (int j = 8; j < 12; j++)
            m[j - 8] = fmaxf(fmaxf(v[j][0], v[j][1]), fmaxf(v[j][2], v[j][3]));
        uint2 o;
        o.x = f16x2_of(m[0], m[1]);
        o.y = f16x2_of(m[2], m[3]);
        *(uint2*)(g_phi16 + (size_t)(b * S4 + t) * 8) = o;
    } else if (ogrp == 1) {
        float m[4];
#pragma unroll
        for (int j = 0; j < 4; j++)
            m[j] = fmaxf(fmaxf(v[j][0], v[j][1]), fmaxf(v[j][2], v[j][3]));
        uint2 o;
        o.x = f16x2_of(m[0], m[1]);
        o.y = f16x2_of(m[2], m[3]);
        *(uint2*)(g_phi16 + (size_t)(b * S4 + t) * 8 + 4) = o;
#pragma unroll
        for (int j = 4; j < 12; j++) {
            float mm = fmaxf(fmaxf(v[j][0], v[j][1]), fmaxf(v[j][2], v[j][3]));
            g_g16[((size_t)b * 32 + (j - 4)) * S4 + t] = __float2half(mm);
        }
    } else {
        int oc0 = (ogrp == 2) ? 8 : 20;
#pragma unroll
        for (int j = 0; j < 12; j++) {
            float mm = fmaxf(fmaxf(v[j][0], v[j][1]), fmaxf(v[j][2], v[j][3]));
            g_g16[((size_t)b * 32 + oc0 + j) * S4 + t] = __float2half(mm);
        }
    }
}

// attention smem offsets (g streamed in 2 halves of 512 keys)
#define PHI_OFF 0                  // 16384 B
#define G_OFF   16384              // 32 oc * GROW = 33280 B
#define GROW    1040               // 512 halves*2B + 16 pad (bank-spread)
#define WO_OFF  49664              // 8192 B
#define L_OFF   57856              // 512 B
#define SMEM_REQ 58368
// O staging reuses the g region after the mainloop (17408 <= 33280)
#define O_OFF   G_OFF
#define OROW    34

// ---------------------------------------------------------------------------
// Attention: warp-level HMMA flash, 3 CTAs/SM. Pass 1 subsampled (phi only).
// Pass 2 in two 512-key phases with g reloaded between.
// ---------------------------------------------------------------------------
__global__ void __launch_bounds__(256, 3) attn_hmma(
    const float* __restrict__ x, const float* __restrict__ w_o,
    const float* __restrict__ gamma_p, float* __restrict__ out)
{
    extern __shared__ char smem[];
    __half* phi_s = (__half*)(smem + PHI_OFF);
    float*  o_s   = (float*)(smem + O_OFF);
    float*  l_s   = (float*)(smem + L_OFF);
    float*  wo_s  = (float*)(smem + WO_OFF);

    const int tid = threadIdx.x;
    const int w   = tid >> 5;
    const int lane = tid & 31;
    const int g   = lane >> 2;
    const int tig = lane & 3;
    const int b   = blockIdx.x >> 5;
    const int q0b = (blockIdx.x & 31) * 128;
    const int qw  = q0b + w * 16;

    {
        const uint4* src = (const uint4*)(g_phi16 + (size_t)b * S4 * 8);
        uint4* dst = (uint4*)phi_s;
        for (int i = tid; i < 1024; i += 256) dst[i] = src[i];
    }
    // g first half (keys 0..511)
    for (int i = tid; i < 2048; i += 256) {
        int oc = i >> 6, j = i & 63;
        uint4 v = *(const uint4*)(g_g16 + ((size_t)b * 32 + oc) * S4 + j * 8);
        *(uint4*)(smem + G_OFF + oc * GROW + j * 16) = v;
    }
    for (int i = tid; i < 512; i += 256)
        ((float4*)wo_s)[i] = ((const float4*)w_o)[i];
    __syncthreads();

    u32 tA0 = *(const u32*)(g_th16 + (size_t)(b * S + qw + g) * 8 + tig * 2);
    u32 tA1 = *(const u32*)(g_th16 + (size_t)(b * S + qw + 8 + g) * 8 + tig * 2);

    // pass 1 (subsampled, phi only): approximate per-query row max
    float m0 = -1e30f, m1 = -1e30f;
#pragma unroll 4
    for (int cb = 0; cb < S4; cb += 64) {
        u32 bA = *(const u32*)(phi_s + (cb + g) * 8 + tig * 2);
        u32 bB = *(const u32*)(phi_s + (cb + 8 + g) * 8 + tig * 2);
        float c0[4] = {0.f, 0.f, 0.f, 0.f};
        float c1[4] = {0.f, 0.f, 0.f, 0.f};
        mma_16n8k8(c0, tA0, tA1, bA);
        mma_16n8k8(c1, tA0, tA1, bB);
        m0 = fmaxf(m0, fmaxf(fmaxf(c0[0], c0[1]), fmaxf(c1[0], c1[1])));
        m1 = fmaxf(m1, fmaxf(fmaxf(c0[2], c0[3]), fmaxf(c1[2], c1[3])));
    }
    m0 = fmaxf(m0, __shfl_xor_sync(0xFFFFFFFF, m0, 1));
    m0 = fmaxf(m0, __shfl_xor_sync(0xFFFFFFFF, m0, 2)) + 2.0f;
    m1 = fmaxf(m1, __shfl_xor_sync(0xFFFFFFFF, m1, 1));
    m1 = fmaxf(m1, __shfl_xor_sync(0xFFFFFFFF, m1, 2)) + 2.0f;

    // pass 2: two phases of 512 keys, g reloaded between
    float o[4][4];
#pragma unroll
    for (int nt = 0; nt < 4; nt++)
#pragma unroll
        for (int j = 0; j < 4; j++) o[nt][j] = 0.f;
    float l0 = 0.f, l1 = 0.f;

    for (int h = 0; h < 2; h++) {
        if (h == 1) {
            __syncthreads();   // everyone done reading g half 0
            for (int i = tid; i < 2048; i += 256) {
                int oc = i >> 6, j = i & 63;
                uint4 v = *(const uint4*)(g_g16 + ((size_t)b * 32 + oc) * S4 + 512 * 8 / 8 + j * 8);
                *(uint4*)(smem + G_OFF + oc * GROW + j * 16) = v;
            }
            __syncthreads();
        }
        const int key0 = h * 512;
#pragma unroll 2
        for (int cc = 0; cc < 512; cc += 16) {
            const int cb = key0 + cc;
            u32 bA = *(const u32*)(phi_s + (cb + g) * 8 + tig * 2);
            u32 bB = *(const u32*)(phi_s + (cb + 8 + g) * 8 + tig * 2);
            float c0[4] = {0.f, 0.f, 0.f, 0.f};
            float c1[4] = {0.f, 0.f, 0.f, 0.f};
            mma_16n8k8(c0, tA0, tA1, bA);
            mma_16n8k8(c1, tA0, tA1, bB);

            float e00 = ex2f(c0[0] - m0), e01 = ex2f(c0[1] - m0);
            float e02 = ex2f(c0[2] - m1), e03 = ex2f(c0[3] - m1);
            float e10 = ex2f(c1[0] - m0), e11 = ex2f(c1[1] - m0);
            float e12 = ex2f(c1[2] - m1), e13 = ex2f(c1[3] - m1);
            l0 += e00 + e01 + e10 + e11;
            l1 += e02 + e03 + e12 + e13;
            u32 pA0 = f16x2_of(e00, e01);
            u32 pA1 = f16x2_of(e02, e03);
            u32 pA2 = f16x2_of(e10, e11);
            u32 pA3 = f16x2_of(e12, e13);

            const char* gbase = smem + G_OFF + (cc + tig * 2) * 2;
#pragma unroll
            for (int nt = 0; nt < 4; nt++) {
                int oc = nt * 8 + g;
                u32 b0 = *(const u32*)(gbase + oc * GROW);
                u32 b1 = *(const u32*)(gbase + oc * GROW + 16);
                mma_16n8k16(o[nt], pA0, pA1, pA2, pA3, b0, b1);
            }
        }
    }

    l0 += __shfl_xor_sync(0xFFFFFFFF, l0, 1);
    l0 += __shfl_xor_sync(0xFFFFFFFF, l0, 2);
    l1 += __shfl_xor_sync(0xFFFFFFFF, l1, 1);
    l1 += __shfl_xor_sync(0xFFFFFFFF, l1, 2);

    __syncthreads();   // everyone done with g half 1 -> reuse region for O
    if (tig == 0) {
        l_s[w * 16 + g] = l0;
        l_s[w * 16 + g + 8] = l1;
    }
#pragma unroll
    for (int nt = 0; nt < 4; nt++) {
        int col = nt * 8 + tig * 2;
        *(float2*)(o_s + (w * 16 + g) * OROW + col)     = make_float2(o[nt][0], o[nt][1]);
        *(float2*)(o_s + (w * 16 + g + 8) * OROW + col) = make_float2(o[nt][2], o[nt][3]);
    }
    __syncthreads();

    int q = tid & 127, half = tid >> 7;
    float n0 = gamma_p[0] / l_s[q];
    ull o2[16];
    {
        const float* op = o_s + q * OROW;
#pragma unroll
        for (int j = 0; j < 16; j++)
            o2[j] = pack2(op[2 * j], op[2 * j + 1]);
    }
    int sidx = q0b + q;
    const float* xr = x + (size_t)b * CHAN * S + sidx;
    float* orow = out + (size_t)b * CHAN * S + sidx;
    for (int co = half * 32; co < half * 32 + 32; co++) {
        const double2* wr = (const double2*)(wo_s + co * 32);
        ull acc = 0ull;
#pragma unroll
        for (int j = 0; j < 8; j++) {
            double2 wv = wr[j];
            acc = ffma2(d2u(wv.x), o2[2 * j], acc);
            acc = ffma2(d2u(wv.y), o2[2 * j + 1], acc);
        }
        float lo, hi;
        unpack2(acc, lo, hi);
        orow[(size_t)co * S] = n0 * (lo + hi) + xr[(size_t)co * S];
    }
}

// ---------------------------------------------------------------------------
extern "C" void kernel_launch(void* const* d_in, const int* in_sizes, int n_in,
                              void* d_out, int out_size)
{
    const float* x       = (const float*)d_in[0];
    const float* w_theta = (const float*)d_in[1];
    const float* w_phi   = (const float*)d_in[2];
    const float* w_g     = (const float*)d_in[3];
    const float* w_o     = (const float*)d_in[4];
    const float* gamma   = (const float*)d_in[5];
    float* out = (float*)d_out;

    cudaFuncSetAttribute(prep_kernel, cudaFuncAttributeMaxDynamicSharedMemorySize, PREP_SMEM);
    prep_kernel<<<256, 256, PREP_SMEM>>>(x, w_theta, w_phi, w_g);

    cudaFuncSetAttribute(attn_hmma, cudaFuncAttributeMaxDynamicSharedMemorySize, SMEM_REQ);
    attn_hmma<<<512, 256, SMEM_REQ>>>(x, w_o, gamma, out);
}

// round 13
// speedup vs baseline: 3.3197x; 1.0035x over previous
#include <cuda_runtime.h>
#include <cuda_fp16.h>

typedef unsigned long long ull;
typedef unsigned int u32;

#define BATCH 16
#define CHAN  64
#define S     4096
#define S4    1024

__device__ __align__(16) __half g_phi16[BATCH * S4 * 8];  // [b][t][8]
__device__ __align__(16) __half g_g16[BATCH * 32 * S4];   // [b][oc][t]
__device__ __align__(16) __half g_th16[BATCH * S * 8];    // [b][s][8] *log2e

// ---------------- helpers ----------------
__device__ __forceinline__ float ex2f(float a) {
    float r; asm("ex2.approx.ftz.f32 %0, %1;" : "=f"(r) : "f"(a)); return r;
}
__device__ __forceinline__ u32 f16x2_of(float lo, float hi) {
    u32 r; asm("cvt.rn.f16x2.f32 %0, %1, %2;" : "=r"(r) : "f"(hi), "f"(lo)); return r;
}
__device__ __forceinline__ u32 h2u(__half2 h) { return *reinterpret_cast<u32*>(&h); }
__device__ __forceinline__ ull pack2(float a, float b) {
    ull r; asm("mov.b64 %0, {%1, %2};" : "=l"(r) : "f"(a), "f"(b)); return r;
}
__device__ __forceinline__ void unpack2(ull v, float& a, float& b) {
    asm("mov.b64 {%0, %1}, %2;" : "=f"(a), "=f"(b) : "l"(v));
}
__device__ __forceinline__ ull ffma2(ull a, ull b, ull c) {
    ull d; asm("fma.rn.f32x2 %0, %1, %2, %3;" : "=l"(d) : "l"(a), "l"(b), "l"(c)); return d;
}
__device__ __forceinline__ ull d2u(double d) { return __double_as_longlong(d); }

__device__ __forceinline__ void mma_16n8k8(float* c, u32 a0, u32 a1, u32 b0) {
    asm volatile("mma.sync.aligned.m16n8k8.row.col.f32.f16.f16.f32 "
        "{%0,%1,%2,%3}, {%4,%5}, {%6}, {%0,%1,%2,%3};"
        : "+f"(c[0]), "+f"(c[1]), "+f"(c[2]), "+f"(c[3])
        : "r"(a0), "r"(a1), "r"(b0));
}
__device__ __forceinline__ void mma_16n8k16(float* c, u32 a0, u32 a1, u32 a2, u32 a3,
                                            u32 b0, u32 b1) {
    asm volatile("mma.sync.aligned.m16n8k16.row.col.f32.f16.f16.f32 "
        "{%0,%1,%2,%3}, {%4,%5,%6,%7}, {%8,%9}, {%0,%1,%2,%3};"
        : "+f"(c[0]), "+f"(c[1]), "+f"(c[2]), "+f"(c[3])
        : "r"(a0), "r"(a1), "r"(a2), "r"(a3), "r"(b0), "r"(b1));
}

// prep kernel dynamic smem
#define PREP_XS_OFF 0
#define PREP_WS_OFF 65536
#define PREP_SMEM   90112

// ---------------------------------------------------------------------------
// Fused prep: 1x1 convs (theta 8, phi 8, g 32) + 2x2 maxpool for phi/g.
// ---------------------------------------------------------------------------
__global__ void __launch_bounds__(256, 2) prep_kernel(
    const float* __restrict__ x, const float* __restrict__ w_theta,
    const float* __restrict__ w_phi, const float* __restrict__ w_g)
{
    extern __shared__ char psm[];
    float* xs = (float*)(psm + PREP_XS_OFF);
    ull*   ws = (ull*)(psm + PREP_WS_OFF);

    const int tid = threadIdx.x;
    const int b   = blockIdx.x >> 4;
    const int rt  = blockIdx.x & 15;

    {
        const float4* src = (const float4*)(x + (size_t)b * CHAN * S + rt * 256);
        for (int i = tid; i < 4096; i += 256) {
            int c = i >> 6, f = i & 63;
            ((float4*)xs)[i] = src[c * (S / 4) + f];
        }
    }
    for (int i = tid; i < 3072; i += 256) {
        int u = i >> 6, c = i & 63;
        float w;
        if (u < 8)        w = w_theta[u * 64 + c] * 1.4426950408889634f;
        else if (u < 16)  w = w_phi[(u - 8) * 64 + c];
        else              w = w_g[(u - 16) * 64 + c];
        ws[i] = pack2(w, w);
    }
    __syncthreads();

    const int pos = tid & 63, ogrp = tid >> 6;
    const int pr = pos >> 5, pc = pos & 31;
    const int u0 = ogrp * 12;

    ull acc[12][2];
#pragma unroll
    for (int j = 0; j < 12; j++) acc[j][0] = acc[j][1] = 0ull;

    const float* xp = xs + (2 * pr) * 64 + 2 * pc;
    const ull* wp = ws + u0 * 64;
#pragma unroll 2
    for (int c = 0; c < CHAN; c++) {
        ull a0 = *(const ull*)(xp + c * 256);
        ull a1 = *(const ull*)(xp + c * 256 + 64);
#pragma unroll
        for (int j = 0; j < 12; j++) {
            ull w = wp[j * 64 + c];
            acc[j][0] = ffma2(a0, w, acc[j][0]);
            acc[j][1] = ffma2(a1, w, acc[j][1]);
        }
    }

    float v[12][4];
#pragma unroll
    for (int j = 0; j < 12; j++) {
        unpack2(acc[j][0], v[j][0], v[j][1]);
        unpack2(acc[j][1], v[j][2], v[j][3]);
    }

    const int t = (rt * 2 + pr) * 32 + pc;
    const int h0 = rt * 4 + 2 * pr, w0c = 2 * pc;

    if (ogrp == 0) {
#pragma unroll
        for (int px = 0; px < 4; px++) {
            int s = (h0 + (px >> 1)) * 64 + w0c + (px & 1);
            uint4 o;
            o.x = f16x2_of(v[0][px], v[1][px]);
            o.y = f16x2_of(v[2][px], v[3][px]);
            o.z = f16x2_of(v[4][px], v[5][px]);
            o.w = f16x2_of(v[6][px], v[7][px]);
            *(uint4*)(g_th16 + (size_t)(b * S + s) * 8) = o;
        }
        float m[4];
#pragma unroll
        for (int j = 8; j < 12; j++)
            m[j - 8] = fmaxf(fmaxf(v[j][0], v[j][1]), fmaxf(v[j][2], v[j][3]));
        uint2 o;
        o.x = f16x2_of(m[0], m[1]);
        o.y = f16x2_of(m[2], m[3]);
        *(uint2*)(g_phi16 + (size_t)(b * S4 + t) * 8) = o;
    } else if (ogrp == 1) {
        float m[4];
#pragma unroll
        for (int j = 0; j < 4; j++)
            m[j] = fmaxf(fmaxf(v[j][0], v[j][1]), fmaxf(v[j][2], v[j][3]));
        uint2 o;
        o.x = f16x2_of(m[0], m[1]);
        o.y = f16x2_of(m[2], m[3]);
        *(uint2*)(g_phi16 + (size_t)(b * S4 + t) * 8 + 4) = o;
#pragma unroll
        for (int j = 4; j < 12; j++) {
            float mm = fmaxf(fmaxf(v[j][0], v[j][1]), fmaxf(v[j][2], v[j][3]));
            g_g16[((size_t)b * 32 + (j - 4)) * S4 + t] = __float2half(mm);
        }
    } else {
        int oc0 = (ogrp == 2) ? 8 : 20;
#pragma unroll
        for (int j = 0; j < 12; j++) {
            float mm = fmaxf(fmaxf(v[j][0], v[j][1]), fmaxf(v[j][2], v[j][3]));
            g_g16[((size_t)b * 32 + oc0 + j) * S4 + t] = __float2half(mm);
        }
    }
}

// attention smem offsets (g streamed in 2 halves of 512 keys)
#define PHI_OFF 0                  // 16384 B
#define G_OFF   16384              // 32 oc * GROW = 33280 B
#define GROW    1040               // 512 halves*2B + 16 pad
#define WO_OFF  49664              // 8192 B
#define L_OFF   57856              // 512 B
#define SMEM_REQ 58368
#define O_OFF   G_OFF              // O staging reuses g region
#define OROW    34

// ---------------------------------------------------------------------------
// Attention: warp-level HMMA flash, 3 CTAs/SM.
//  - max-subtract folded into MMA1 accumulator init (C = -m)
//  - l computed by a 5th MMA2 against fp16 ones (row-sums of P)
// ---------------------------------------------------------------------------
__global__ void __launch_bounds__(256, 3) attn_hmma(
    const float* __restrict__ x, const float* __restrict__ w_o,
    const float* __restrict__ gamma_p, float* __restrict__ out)
{
    extern __shared__ char smem[];
    __half* phi_s = (__half*)(smem + PHI_OFF);
    float*  o_s   = (float*)(smem + O_OFF);
    float*  l_s   = (float*)(smem + L_OFF);
    float*  wo_s  = (float*)(smem + WO_OFF);

    const int tid = threadIdx.x;
    const int w   = tid >> 5;
    const int lane = tid & 31;
    const int g   = lane >> 2;
    const int tig = lane & 3;
    const int b   = blockIdx.x >> 5;
    const int q0b = (blockIdx.x & 31) * 128;
    const int qw  = q0b + w * 16;

    {
        const uint4* src = (const uint4*)(g_phi16 + (size_t)b * S4 * 8);
        uint4* dst = (uint4*)phi_s;
        for (int i = tid; i < 1024; i += 256) dst[i] = src[i];
    }
    for (int i = tid; i < 2048; i += 256) {      // g keys 0..511
        int oc = i >> 6, j = i & 63;
        uint4 v = *(const uint4*)(g_g16 + ((size_t)b * 32 + oc) * S4 + j * 8);
        *(uint4*)(smem + G_OFF + oc * GROW + j * 16) = v;
    }
    for (int i = tid; i < 512; i += 256)
        ((float4*)wo_s)[i] = ((const float4*)w_o)[i];
    __syncthreads();

    u32 tA0 = *(const u32*)(g_th16 + (size_t)(b * S + qw + g) * 8 + tig * 2);
    u32 tA1 = *(const u32*)(g_th16 + (size_t)(b * S + qw + 8 + g) * 8 + tig * 2);

    // pass 1 (subsampled, phi only): approximate per-query row max
    float m0 = -1e30f, m1 = -1e30f;
#pragma unroll 4
    for (int cb = 0; cb < S4; cb += 64) {
        u32 bA = *(const u32*)(phi_s + (cb + g) * 8 + tig * 2);
        u32 bB = *(const u32*)(phi_s + (cb + 8 + g) * 8 + tig * 2);
        float c0[4] = {0.f, 0.f, 0.f, 0.f};
        float c1[4] = {0.f, 0.f, 0.f, 0.f};
        mma_16n8k8(c0, tA0, tA1, bA);
        mma_16n8k8(c1, tA0, tA1, bB);
        m0 = fmaxf(m0, fmaxf(fmaxf(c0[0], c0[1]), fmaxf(c1[0], c1[1])));
        m1 = fmaxf(m1, fmaxf(fmaxf(c0[2], c0[3]), fmaxf(c1[2], c1[3])));
    }
    m0 = fmaxf(m0, __shfl_xor_sync(0xFFFFFFFF, m0, 1));
    m0 = fmaxf(m0, __shfl_xor_sync(0xFFFFFFFF, m0, 2)) + 2.0f;
    m1 = fmaxf(m1, __shfl_xor_sync(0xFFFFFFFF, m1, 1));
    m1 = fmaxf(m1, __shfl_xor_sync(0xFFFFFFFF, m1, 2)) + 2.0f;
    const float nm0 = -m0, nm1 = -m1;

    // pass 2
    float o[4][4];
#pragma unroll
    for (int nt = 0; nt < 4; nt++)
#pragma unroll
        for (int j = 0; j < 4; j++) o[nt][j] = 0.f;
    float lacc[4] = {0.f, 0.f, 0.f, 0.f};
    const u32 ONES = 0x3C003C00u;   // fp16 {1,1}

    for (int h = 0; h < 2; h++) {
        if (h == 1) {
            __syncthreads();
            for (int i = tid; i < 2048; i += 256) {
                int oc = i >> 6, j = i & 63;
                uint4 v = *(const uint4*)(g_g16 + ((size_t)b * 32 + oc) * S4 + 512 + j * 8);
                *(uint4*)(smem + G_OFF + oc * GROW + j * 16) = v;
            }
            __syncthreads();
        }
        const int key0 = h * 512;
#pragma unroll 2
        for (int cc = 0; cc < 512; cc += 16) {
            const int cb = key0 + cc;
            u32 bA = *(const u32*)(phi_s + (cb + g) * 8 + tig * 2);
            u32 bB = *(const u32*)(phi_s + (cb + 8 + g) * 8 + tig * 2);
            // C preloaded with -m: MMA emits s - m directly
            float c0[4] = {nm0, nm0, nm1, nm1};
            float c1[4] = {nm0, nm0, nm1, nm1};
            mma_16n8k8(c0, tA0, tA1, bA);
            mma_16n8k8(c1, tA0, tA1, bB);

            u32 pA0 = f16x2_of(ex2f(c0[0]), ex2f(c0[1]));
            u32 pA1 = f16x2_of(ex2f(c0[2]), ex2f(c0[3]));
            u32 pA2 = f16x2_of(ex2f(c1[0]), ex2f(c1[1]));
            u32 pA3 = f16x2_of(ex2f(c1[2]), ex2f(c1[3]));

            const char* gbase = smem + G_OFF + (cc + tig * 2) * 2;
#pragma unroll
            for (int nt = 0; nt < 4; nt++) {
                int oc = nt * 8 + g;
                u32 b0 = *(const u32*)(gbase + oc * GROW);
                u32 b1 = *(const u32*)(gbase + oc * GROW + 16);
                mma_16n8k16(o[nt], pA0, pA1, pA2, pA3, b0, b1);
            }
            // l: row-sums of P via ones-B (all output columns identical)
            mma_16n8k16(lacc, pA0, pA1, pA2, pA3, ONES, ONES);
        }
    }

    __syncthreads();   // done with g half 1 -> reuse region for O staging
    if (tig == 0) {
        l_s[w * 16 + g] = lacc[0];
        l_s[w * 16 + g + 8] = lacc[2];
    }
#pragma unroll
    for (int nt = 0; nt < 4; nt++) {
        int col = nt * 8 + tig * 2;
        *(float2*)(o_s + (w * 16 + g) * OROW + col)     = make_float2(o[nt][0], o[nt][1]);
        *(float2*)(o_s + (w * 16 + g + 8) * OROW + col) = make_float2(o[nt][2], o[nt][3]);
    }
    __syncthreads();

    int q = tid & 127, half = tid >> 7;
    float n0 = gamma_p[0] / l_s[q];
    ull o2[16];
    {
        const float* op = o_s + q * OROW;
#pragma unroll
        for (int j = 0; j < 16; j++)
            o2[j] = pack2(op[2 * j], op[2 * j + 1]);
    }
    int sidx = q0b + q;
    const float* xr = x + (size_t)b * CHAN * S + sidx;
    float* orow = out + (size_t)b * CHAN * S + sidx;
    for (int co = half * 32; co < half * 32 + 32; co++) {
        const double2* wr = (const double2*)(wo_s + co * 32);
        ull acc = 0ull;
#pragma unroll
        for (int j = 0; j < 8; j++) {
            double2 wv = wr[j];
            acc = ffma2(d2u(wv.x), o2[2 * j], acc);
            acc = ffma2(d2u(wv.y), o2[2 * j + 1], acc);
        }
        float lo, hi;
        unpack2(acc, lo, hi);
        orow[(size_t)co * S] = n0 * (lo + hi) + xr[(size_t)co * S];
    }
}

// ---------------------------------------------------------------------------
extern "C" void kernel_launch(void* const* d_in, const int* in_sizes, int n_in,
                              void* d_out, int out_size)
{
    const float* x       = (const float*)d_in[0];
    const float* w_theta = (const float*)d_in[1];
    const float* w_phi   = (const float*)d_in[2];
    const float* w_g     = (const float*)d_in[3];
    const float* w_o     = (const float*)d_in[4];
    const float* gamma   = (const float*)d_in[5];
    float* out = (float*)d_out;

    cudaFuncSetAttribute(prep_kernel, cudaFuncAttributeMaxDynamicSharedMemorySize, PREP_SMEM);
    prep_kernel<<<256, 256, PREP_SMEM>>>(x, w_theta, w_phi, w_g);

    cudaFuncSetAttribute(attn_hmma, cudaFuncAttributeMaxDynamicSharedMemorySize, SMEM_REQ);
    attn_hmma<<<512, 256, SMEM_REQ>>>(x, w_o, gamma, out);
}

// round 14
// speedup vs baseline: 3.5013x; 1.0547x over previous
#include <cuda_runtime.h>
#include <cuda_fp16.h>

typedef unsigned long long ull;
typedef unsigned int u32;

#define BATCH 16
#define CHAN  64
#define S     4096
#define S4    1024

__device__ __align__(16) __half g_phi16[BATCH * S4 * 8];  // [b][t][8]
__device__ __align__(16) __half g_g16[BATCH * 32 * S4];   // [b][oc][t] pair-interleaved
__device__ __align__(16) __half g_th16[BATCH * S * 8];    // [b][s][8] *log2e

// ---------------- helpers ----------------
__device__ __forceinline__ float ex2f(float a) {
    float r; asm("ex2.approx.ftz.f32 %0, %1;" : "=f"(r) : "f"(a)); return r;
}
__device__ __forceinline__ u32 f16x2_of(float lo, float hi) {
    u32 r; asm("cvt.rn.f16x2.f32 %0, %1, %2;" : "=r"(r) : "f"(hi), "f"(lo)); return r;
}
__device__ __forceinline__ u32 h2u(__half2 h) { return *reinterpret_cast<u32*>(&h); }
__device__ __forceinline__ ull pack2(float a, float b) {
    ull r; asm("mov.b64 %0, {%1, %2};" : "=l"(r) : "f"(a), "f"(b)); return r;
}
__device__ __forceinline__ void unpack2(ull v, float& a, float& b) {
    asm("mov.b64 {%0, %1}, %2;" : "=f"(a), "=f"(b) : "l"(v));
}
__device__ __forceinline__ ull ffma2(ull a, ull b, ull c) {
    ull d; asm("fma.rn.f32x2 %0, %1, %2, %3;" : "=l"(d) : "l"(a), "l"(b), "l"(c)); return d;
}
__device__ __forceinline__ ull d2u(double d) { return __double_as_longlong(d); }

// pair-interleave within each 16-key chunk: u32 j -> slot ((j&3)<<1)|(j>>2)
// so (k, k+8) f16 pairs land in adjacent u32 slots (one LDS.64 per fragment).
__device__ __forceinline__ int gidx16(int t) {
    int wi = t & 15, j = wi >> 1, lo = wi & 1;
    int j2 = ((j & 3) << 1) | (j >> 2);
    return (t & ~15) | (j2 << 1) | lo;
}

__device__ __forceinline__ void mma_16n8k8(float* c, u32 a0, u32 a1, u32 b0) {
    asm volatile("mma.sync.aligned.m16n8k8.row.col.f32.f16.f16.f32 "
        "{%0,%1,%2,%3}, {%4,%5}, {%6}, {%0,%1,%2,%3};"
        : "+f"(c[0]), "+f"(c[1]), "+f"(c[2]), "+f"(c[3])
        : "r"(a0), "r"(a1), "r"(b0));
}
__device__ __forceinline__ void mma_16n8k16(float* c, u32 a0, u32 a1, u32 a2, u32 a3,
                                            u32 b0, u32 b1) {
    asm volatile("mma.sync.aligned.m16n8k16.row.col.f32.f16.f16.f32 "
        "{%0,%1,%2,%3}, {%4,%5,%6,%7}, {%8,%9}, {%0,%1,%2,%3};"
        : "+f"(c[0]), "+f"(c[1]), "+f"(c[2]), "+f"(c[3])
        : "r"(a0), "r"(a1), "r"(a2), "r"(a3), "r"(b0), "r"(b1));
}

// prep kernel dynamic smem
#define PREP_XS_OFF 0
#define PREP_WS_OFF 65536
#define PREP_SMEM   90112

// ---------------------------------------------------------------------------
// Fused prep: 1x1 convs (theta 8, phi 8, g 32) + 2x2 maxpool for phi/g.
// g written with pair-interleaved key index (gidx16).
// ---------------------------------------------------------------------------
__global__ void __launch_bounds__(256, 2) prep_kernel(
    const float* __restrict__ x, const float* __restrict__ w_theta,
    const float* __restrict__ w_phi, const float* __restrict__ w_g)
{
    extern __shared__ char psm[];
    float* xs = (float*)(psm + PREP_XS_OFF);
    ull*   ws = (ull*)(psm + PREP_WS_OFF);

    const int tid = threadIdx.x;
    const int b   = blockIdx.x >> 4;
    const int rt  = blockIdx.x & 15;

    {
        const float4* src = (const float4*)(x + (size_t)b * CHAN * S + rt * 256);
        for (int i = tid; i < 4096; i += 256) {
            int c = i >> 6, f = i & 63;
            ((float4*)xs)[i] = src[c * (S / 4) + f];
        }
    }
    for (int i = tid; i < 3072; i += 256) {
        int u = i >> 6, c = i & 63;
        float w;
        if (u < 8)        w = w_theta[u * 64 + c] * 1.4426950408889634f;
        else if (u < 16)  w = w_phi[(u - 8) * 64 + c];
        else              w = w_g[(u - 16) * 64 + c];
        ws[i] = pack2(w, w);
    }
    __syncthreads();

    const int pos = tid & 63, ogrp = tid >> 6;
    const int pr = pos >> 5, pc = pos & 31;
    const int u0 = ogrp * 12;

    ull acc[12][2];
#pragma unroll
    for (int j = 0; j < 12; j++) acc[j][0] = acc[j][1] = 0ull;

    const float* xp = xs + (2 * pr) * 64 + 2 * pc;
    const ull* wp = ws + u0 * 64;
#pragma unroll 2
    for (int c = 0; c < CHAN; c++) {
        ull a0 = *(const ull*)(xp + c * 256);
        ull a1 = *(const ull*)(xp + c * 256 + 64);
#pragma unroll
        for (int j = 0; j < 12; j++) {
            ull w = wp[j * 64 + c];
            acc[j][0] = ffma2(a0, w, acc[j][0]);
            acc[j][1] = ffma2(a1, w, acc[j][1]);
        }
    }

    float v[12][4];
#pragma unroll
    for (int j = 0; j < 12; j++) {
        unpack2(acc[j][0], v[j][0], v[j][1]);
        unpack2(acc[j][1], v[j][2], v[j][3]);
    }

    const int t = (rt * 2 + pr) * 32 + pc;
    const int ti = gidx16(t);
    const int h0 = rt * 4 + 2 * pr, w0c = 2 * pc;

    if (ogrp == 0) {
#pragma unroll
        for (int px = 0; px < 4; px++) {
            int s = (h0 + (px >> 1)) * 64 + w0c + (px & 1);
            uint4 o;
            o.x = f16x2_of(v[0][px], v[1][px]);
            o.y = f16x2_of(v[2][px], v[3][px]);
            o.z = f16x2_of(v[4][px], v[5][px]);
            o.w = f16x2_of(v[6][px], v[7][px]);
            *(uint4*)(g_th16 + (size_t)(b * S + s) * 8) = o;
        }
        float m[4];
#pragma unroll
        for (int j = 8; j < 12; j++)
            m[j - 8] = fmaxf(fmaxf(v[j][0], v[j][1]), fmaxf(v[j][2], v[j][3]));
        uint2 o;
        o.x = f16x2_of(m[0], m[1]);
        o.y = f16x2_of(m[2], m[3]);
        *(uint2*)(g_phi16 + (size_t)(b * S4 + t) * 8) = o;
    } else if (ogrp == 1) {
        float m[4];
#pragma unroll
        for (int j = 0; j < 4; j++)
            m[j] = fmaxf(fmaxf(v[j][0], v[j][1]), fmaxf(v[j][2], v[j][3]));
        uint2 o;
        o.x = f16x2_of(m[0], m[1]);
        o.y = f16x2_of(m[2], m[3]);
        *(uint2*)(g_phi16 + (size_t)(b * S4 + t) * 8 + 4) = o;
#pragma unroll
        for (int j = 4; j < 12; j++) {
            float mm = fmaxf(fmaxf(v[j][0], v[j][1]), fmaxf(v[j][2], v[j][3]));
            g_g16[((size_t)b * 32 + (j - 4)) * S4 + ti] = __float2half(mm);
        }
    } else {
        int oc0 = (ogrp == 2) ? 8 : 20;
#pragma unroll
        for (int j = 0; j < 12; j++) {
            float mm = fmaxf(fmaxf(v[j][0], v[j][1]), fmaxf(v[j][2], v[j][3]));
            g_g16[((size_t)b * 32 + oc0 + j) * S4 + ti] = __float2half(mm);
        }
    }
}

// attention smem offsets
#define PHI_OFF  0                 // 16384 B
#define G_OFF    16384             // 32 oc * GROW = 33280 B
#define GROW     1040
#define WO16_OFF 49664             // fp16 w_o [64][36] = 4608 B
#define SMEM_REQ 54272
#define OUT_OFF  G_OFF             // result staging [128 q][65 floats] = 33280 B

// ---------------------------------------------------------------------------
// Attention: warp-level HMMA flash, 3 CTAs/SM.
//  - max folded into MMA1 C-init; l via ones-MMA2; w_o epilogue via MMA3
//  - g pair-interleaved: one LDS.64 per B fragment pair
// ---------------------------------------------------------------------------
__global__ void __launch_bounds__(256, 3) attn_hmma(
    const float* __restrict__ x, const float* __restrict__ w_o,
    const float* __restrict__ gamma_p, float* __restrict__ out)
{
    extern __shared__ char smem[];
    __half* phi_s = (__half*)(smem + PHI_OFF);
    __half* wo16  = (__half*)(smem + WO16_OFF);
    float*  out_s = (float*)(smem + OUT_OFF);

    const int tid = threadIdx.x;
    const int w   = tid >> 5;
    const int lane = tid & 31;
    const int g   = lane >> 2;
    const int tig = lane & 3;
    const int b   = blockIdx.x >> 5;
    const int q0b = (blockIdx.x & 31) * 128;
    const int qw  = q0b + w * 16;

    {
        const uint4* src = (const uint4*)(g_phi16 + (size_t)b * S4 * 8);
        uint4* dst = (uint4*)phi_s;
        for (int i = tid; i < 1024; i += 256) dst[i] = src[i];
    }
    for (int i = tid; i < 2048; i += 256) {      // g keys 0..511 (layout preserved)
        int oc = i >> 6, j = i & 63;
        uint4 v = *(const uint4*)(g_g16 + ((size_t)b * 32 + oc) * S4 + j * 8);
        *(uint4*)(smem + G_OFF + oc * GROW + j * 16) = v;
    }
    for (int i = tid; i < 2048; i += 256) {      // w_o -> fp16, padded rows of 36
        int co = i >> 5, k = i & 31;
        wo16[co * 36 + k] = __float2half(w_o[co * 32 + k]);
    }
    __syncthreads();

    u32 tA0 = *(const u32*)(g_th16 + (size_t)(b * S + qw + g) * 8 + tig * 2);
    u32 tA1 = *(const u32*)(g_th16 + (size_t)(b * S + qw + 8 + g) * 8 + tig * 2);

    // pass 1 (subsampled, phi only): approximate per-query row max
    float m0 = -1e30f, m1 = -1e30f;
#pragma unroll 4
    for (int cb = 0; cb < S4; cb += 64) {
        u32 bA = *(const u32*)(phi_s + (cb + g) * 8 + tig * 2);
        u32 bB = *(const u32*)(phi_s + (cb + 8 + g) * 8 + tig * 2);
        float c0[4] = {0.f, 0.f, 0.f, 0.f};
        float c1[4] = {0.f, 0.f, 0.f, 0.f};
        mma_16n8k8(c0, tA0, tA1, bA);
        mma_16n8k8(c1, tA0, tA1, bB);
        m0 = fmaxf(m0, fmaxf(fmaxf(c0[0], c0[1]), fmaxf(c1[0], c1[1])));
        m1 = fmaxf(m1, fmaxf(fmaxf(c0[2], c0[3]), fmaxf(c1[2], c1[3])));
    }
    m0 = fmaxf(m0, __shfl_xor_sync(0xFFFFFFFF, m0, 1));
    m0 = fmaxf(m0, __shfl_xor_sync(0xFFFFFFFF, m0, 2)) + 2.0f;
    m1 = fmaxf(m1, __shfl_xor_sync(0xFFFFFFFF, m1, 1));
    m1 = fmaxf(m1, __shfl_xor_sync(0xFFFFFFFF, m1, 2)) + 2.0f;
    const float nm0 = -m0, nm1 = -m1;

    // pass 2
    float o[4][4];
#pragma unroll
    for (int nt = 0; nt < 4; nt++)
#pragma unroll
        for (int j = 0; j < 4; j++) o[nt][j] = 0.f;
    float lacc[4] = {0.f, 0.f, 0.f, 0.f};
    const u32 ONES = 0x3C003C00u;

    for (int h = 0; h < 2; h++) {
        if (h == 1) {
            __syncthreads();
            for (int i = tid; i < 2048; i += 256) {
                int oc = i >> 6, j = i & 63;
                uint4 v = *(const uint4*)(g_g16 + ((size_t)b * 32 + oc) * S4 + 512 + j * 8);
                *(uint4*)(smem + G_OFF + oc * GROW + j * 16) = v;
            }
            __syncthreads();
        }
        const int key0 = h * 512;
#pragma unroll 2
        for (int cc = 0; cc < 512; cc += 16) {
            const int cb = key0 + cc;
            u32 bA = *(const u32*)(phi_s + (cb + g) * 8 + tig * 2);
            u32 bB = *(const u32*)(phi_s + (cb + 8 + g) * 8 + tig * 2);
            float c0[4] = {nm0, nm0, nm1, nm1};
            float c1[4] = {nm0, nm0, nm1, nm1};
            mma_16n8k8(c0, tA0, tA1, bA);
            mma_16n8k8(c1, tA0, tA1, bB);

            u32 pA0 = f16x2_of(ex2f(c0[0]), ex2f(c0[1]));
            u32 pA1 = f16x2_of(ex2f(c0[2]), ex2f(c0[3]));
            u32 pA2 = f16x2_of(ex2f(c1[0]), ex2f(c1[1]));
            u32 pA3 = f16x2_of(ex2f(c1[2]), ex2f(c1[3]));

            const char* gb = smem + G_OFF + cc * 2 + tig * 8;
#pragma unroll
            for (int nt = 0; nt < 4; nt++) {
                int oc = nt * 8 + g;
                ull bv = *(const ull*)(gb + oc * GROW);
                mma_16n8k16(o[nt], pA0, pA1, pA2, pA3, (u32)bv, (u32)(bv >> 32));
            }
            mma_16n8k16(lacc, pA0, pA1, pA2, pA3, ONES, ONES);
        }
    }

    __syncthreads();   // done with g -> region becomes out_s

    // ---- epilogue MMA3: out = (gamma/l) * (o @ w_o^T) ----
    const float gamma = gamma_p[0];
    const float inv0 = gamma / lacc[0];   // row g
    const float inv1 = gamma / lacc[2];   // row g+8

    u32 a3[2][4];
#pragma unroll
    for (int ks = 0; ks < 2; ks++) {
        const float* oA = o[2 * ks];
        const float* oB = o[2 * ks + 1];
        a3[ks][0] = f16x2_of(oA[0] * inv0, oA[1] * inv0);
        a3[ks][1] = f16x2_of(oA[2] * inv1, oA[3] * inv1);
        a3[ks][2] = f16x2_of(oB[0] * inv0, oB[1] * inv0);
        a3[ks][3] = f16x2_of(oB[2] * inv1, oB[3] * inv1);
    }
    const int r0 = w * 16 + g, r1 = r0 + 8;
#pragma unroll
    for (int nt3 = 0; nt3 < 8; nt3++) {
        int co = nt3 * 8 + g;
        float rc[4] = {0.f, 0.f, 0.f, 0.f};
#pragma unroll
        for (int ks = 0; ks < 2; ks++) {
            u32 b0 = *(const u32*)(wo16 + co * 36 + ks * 16 + tig * 2);
            u32 b1 = *(const u32*)(wo16 + co * 36 + ks * 16 + 8 + tig * 2);
            mma_16n8k16(rc, a3[ks][0], a3[ks][1], a3[ks][2], a3[ks][3], b0, b1);
        }
        int col = nt3 * 8 + tig * 2;
        out_s[r0 * 65 + col]     = rc[0];
        out_s[r0 * 65 + col + 1] = rc[1];
        out_s[r1 * 65 + col]     = rc[2];
        out_s[r1 * 65 + col + 1] = rc[3];
    }
    __syncthreads();

    // ---- coalesced residual-add writeback ----
    const float* xb = x + (size_t)b * CHAN * S;
    float* ob = out + (size_t)b * CHAN * S;
#pragma unroll 4
    for (int k = 0; k < 32; k++) {
        int i = tid + k * 256;
        int q = i & 127, ch = i >> 7;
        int s = q0b + q;
        ob[(size_t)ch * S + s] = out_s[q * 65 + ch] + xb[(size_t)ch * S + s];
    }
}

// ---------------------------------------------------------------------------
extern "C" void kernel_launch(void* const* d_in, const int* in_sizes, int n_in,
                              void* d_out, int out_size)
{
    const float* x       = (const float*)d_in[0];
    const float* w_theta = (const float*)d_in[1];
    const float* w_phi   = (const float*)d_in[2];
    const float* w_g     = (const float*)d_in[3];
    const float* w_o     = (const float*)d_in[4];
    const float* gamma   = (const float*)d_in[5];
    float* out = (float*)d_out;

    cudaFuncSetAttribute(prep_kernel, cudaFuncAttributeMaxDynamicSharedMemorySize, PREP_SMEM);
    prep_kernel<<<256, 256, PREP_SMEM>>>(x, w_theta, w_phi, w_g);

    cudaFuncSetAttribute(attn_hmma, cudaFuncAttributeMaxDynamicSharedMemorySize, SMEM_REQ);
    attn_hmma<<<512, 256, SMEM_REQ>>>(x, w_o, gamma, out);
}

// round 16
// speedup vs baseline: 3.6205x; 1.0340x over previous
#include <cuda_runtime.h>
#include <cuda_fp16.h>

typedef unsigned long long ull;
typedef unsigned int u32;

#define BATCH 16
#define CHAN  64
#define S     4096
#define S4    1024

__device__ __align__(16) __half g_phi16[BATCH * S4 * 8];  // [b][t][8]
__device__ __align__(16) __half g_g16[BATCH * 32 * S4];   // [b][oc][t] pair-interleaved
__device__ __align__(16) __half g_th16[BATCH * S * 8];    // [b][s][8] *log2e

// ---------------- helpers ----------------
__device__ __forceinline__ float ex2f(float a) {
    float r; asm("ex2.approx.ftz.f32 %0, %1;" : "=f"(r) : "f"(a)); return r;
}
__device__ __forceinline__ u32 f16x2_of(float lo, float hi) {
    u32 r; asm("cvt.rn.f16x2.f32 %0, %1, %2;" : "=r"(r) : "f"(hi), "f"(lo)); return r;
}
__device__ __forceinline__ u32 h2u(__half2 h) { return *reinterpret_cast<u32*>(&h); }
__device__ __forceinline__ ull pack2(float a, float b) {
    ull r; asm("mov.b64 %0, {%1, %2};" : "=l"(r) : "f"(a), "f"(b)); return r;
}
__device__ __forceinline__ void unpack2(ull v, float& a, float& b) {
    asm("mov.b64 {%0, %1}, %2;" : "=f"(a), "=f"(b) : "l"(v));
}
__device__ __forceinline__ ull ffma2(ull a, ull b, ull c) {
    ull d; asm("fma.rn.f32x2 %0, %1, %2, %3;" : "=l"(d) : "l"(a), "l"(b), "l"(c)); return d;
}
__device__ __forceinline__ ull d2u(double d) { return __double_as_longlong(d); }

// pair-interleave within each 16-key chunk: u32 j -> slot ((j&3)<<1)|(j>>2)
__device__ __forceinline__ int gidx16(int t) {
    int wi = t & 15, j = wi >> 1, lo = wi & 1;
    int j2 = ((j & 3) << 1) | (j >> 2);
    return (t & ~15) | (j2 << 1) | lo;
}

__device__ __forceinline__ void mma_16n8k8(float* c, u32 a0, u32 a1, u32 b0) {
    asm volatile("mma.sync.aligned.m16n8k8.row.col.f32.f16.f16.f32 "
        "{%0,%1,%2,%3}, {%4,%5}, {%6}, {%0,%1,%2,%3};"
        : "+f"(c[0]), "+f"(c[1]), "+f"(c[2]), "+f"(c[3])
        : "r"(a0), "r"(a1), "r"(b0));
}
__device__ __forceinline__ void mma_16n8k16(float* c, u32 a0, u32 a1, u32 a2, u32 a3,
                                            u32 b0, u32 b1) {
    asm volatile("mma.sync.aligned.m16n8k16.row.col.f32.f16.f16.f32 "
        "{%0,%1,%2,%3}, {%4,%5,%6,%7}, {%8,%9}, {%0,%1,%2,%3};"
        : "+f"(c[0]), "+f"(c[1]), "+f"(c[2]), "+f"(c[3])
        : "r"(a0), "r"(a1), "r"(a2), "r"(a3), "r"(b0), "r"(b1));
}

// prep kernel dynamic smem
#define PREP_XS_OFF 0
#define PREP_WS_OFF 65536
#define PREP_SMEM   90112

// ---------------------------------------------------------------------------
// Fused prep: 1x1 convs (theta 8, phi 8, g 32) + 2x2 maxpool for phi/g.
// ---------------------------------------------------------------------------
__global__ void __launch_bounds__(256, 2) prep_kernel(
    const float* __restrict__ x, const float* __restrict__ w_theta,
    const float* __restrict__ w_phi, const float* __restrict__ w_g)
{
    extern __shared__ char psm[];
    float* xs = (float*)(psm + PREP_XS_OFF);
    ull*   ws = (ull*)(psm + PREP_WS_OFF);

    const int tid = threadIdx.x;
    const int b   = blockIdx.x >> 4;
    const int rt  = blockIdx.x & 15;

    {
        const float4* src = (const float4*)(x + (size_t)b * CHAN * S + rt * 256);
        for (int i = tid; i < 4096; i += 256) {
            int c = i >> 6, f = i & 63;
            ((float4*)xs)[i] = src[c * (S / 4) + f];
        }
    }
    for (int i = tid; i < 3072; i += 256) {
        int u = i >> 6, c = i & 63;
        float w;
        if (u < 8)        w = w_theta[u * 64 + c] * 1.4426950408889634f;
        else if (u < 16)  w = w_phi[(u - 8) * 64 + c];
        else              w = w_g[(u - 16) * 64 + c];
        ws[i] = pack2(w, w);
    }
    __syncthreads();

    const int pos = tid & 63, ogrp = tid >> 6;
    const int pr = pos >> 5, pc = pos & 31;
    const int u0 = ogrp * 12;

    ull acc[12][2];
#pragma unroll
    for (int j = 0; j < 12; j++) acc[j][0] = acc[j][1] = 0ull;

    const float* xp = xs + (2 * pr) * 64 + 2 * pc;
    const ull* wp = ws + u0 * 64;
#pragma unroll 2
    for (int c = 0; c < CHAN; c++) {
        ull a0 = *(const ull*)(xp + c * 256);
        ull a1 = *(const ull*)(xp + c * 256 + 64);
#pragma unroll
        for (int j = 0; j < 12; j++) {
            ull w = wp[j * 64 + c];
            acc[j][0] = ffma2(a0, w, acc[j][0]);
            acc[j][1] = ffma2(a1, w, acc[j][1]);
        }
    }

    float v[12][4];
#pragma unroll
    for (int j = 0; j < 12; j++) {
        unpack2(acc[j][0], v[j][0], v[j][1]);
        unpack2(acc[j][1], v[j][2], v[j][3]);
    }

    const int t = (rt * 2 + pr) * 32 + pc;
    const int ti = gidx16(t);
    const int h0 = rt * 4 + 2 * pr, w0c = 2 * pc;

    if (ogrp == 0) {
#pragma unroll
        for (int px = 0; px < 4; px++) {
            int s = (h0 + (px >> 1)) * 64 + w0c + (px & 1);
            uint4 o;
            o.x = f16x2_of(v[0][px], v[1][px]);
            o.y = f16x2_of(v[2][px], v[3][px]);
            o.z = f16x2_of(v[4][px], v[5][px]);
            o.w = f16x2_of(v[6][px], v[7][px]);
            *(uint4*)(g_th16 + (size_t)(b * S + s) * 8) = o;
        }
        float m[4];
#pragma unroll
        for (int j = 8; j < 12; j++)
            m[j - 8] = fmaxf(fmaxf(v[j][0], v[j][1]), fmaxf(v[j][2], v[j][3]));
        uint2 o;
        o.x = f16x2_of(m[0], m[1]);
        o.y = f16x2_of(m[2], m[3]);
        *(uint2*)(g_phi16 + (size_t)(b * S4 + t) * 8) = o;
    } else if (ogrp == 1) {
        float m[4];
#pragma unroll
        for (int j = 0; j < 4; j++)
            m[j] = fmaxf(fmaxf(v[j][0], v[j][1]), fmaxf(v[j][2], v[j][3]));
        uint2 o;
        o.x = f16x2_of(m[0], m[1]);
        o.y = f16x2_of(m[2], m[3]);
        *(uint2*)(g_phi16 + (size_t)(b * S4 + t) * 8 + 4) = o;
#pragma unroll
        for (int j = 4; j < 12; j++) {
            float mm = fmaxf(fmaxf(v[j][0], v[j][1]), fmaxf(v[j][2], v[j][3]));
            g_g16[((size_t)b * 32 + (j - 4)) * S4 + ti] = __float2half(mm);
        }
    } else {
        int oc0 = (ogrp == 2) ? 8 : 20;
#pragma unroll
        for (int j = 0; j < 12; j++) {
            float mm = fmaxf(fmaxf(v[j][0], v[j][1]), fmaxf(v[j][2], v[j][3]));
            g_g16[((size_t)b * 32 + oc0 + j) * S4 + ti] = __float2half(mm);
        }
    }
}

// attention smem offsets
#define PHI_OFF  0                 // 16384 B
#define G_OFF    16384             // 32 oc * GROW = 33280 B
#define GROW     1040
#define WO16_OFF 49664             // fp16 w_o [64][36] = 4608 B
#define SMEM_REQ 54272
#define OUT_OFF  G_OFF             // result staging [128 q][65 floats]

// ---------------------------------------------------------------------------
// Attention: warp-level HMMA flash, 4 CTAs/SM (single wave, grid 512 <= 592).
//  - max folded into MMA1 C-init; l via ones-MMA2; w_o epilogue via MMA3
// ---------------------------------------------------------------------------
__global__ void __launch_bounds__(256, 4) attn_hmma(
    const float* __restrict__ x, const float* __restrict__ w_o,
    const float* __restrict__ gamma_p, float* __restrict__ out)
{
    extern __shared__ char smem[];
    __half* phi_s = (__half*)(smem + PHI_OFF);
    __half* wo16  = (__half*)(smem + WO16_OFF);
    float*  out_s = (float*)(smem + OUT_OFF);

    const int tid = threadIdx.x;
    const int w   = tid >> 5;
    const int lane = tid & 31;
    const int g   = lane >> 2;
    const int tig = lane & 3;
    const int b   = blockIdx.x >> 5;
    const int q0b = (blockIdx.x & 31) * 128;
    const int qw  = q0b + w * 16;

    {
        const uint4* src = (const uint4*)(g_phi16 + (size_t)b * S4 * 8);
        uint4* dst = (uint4*)phi_s;
        for (int i = tid; i < 1024; i += 256) dst[i] = src[i];
    }
    for (int i = tid; i < 2048; i += 256) {
        int oc = i >> 6, j = i & 63;
        uint4 v = *(const uint4*)(g_g16 + ((size_t)b * 32 + oc) * S4 + j * 8);
        *(uint4*)(smem + G_OFF + oc * GROW + j * 16) = v;
    }
    for (int i = tid; i < 2048; i += 256) {
        int co = i >> 5, k = i & 31;
        wo16[co * 36 + k] = __float2half(w_o[co * 32 + k]);
    }
    __syncthreads();

    u32 tA0 = *(const u32*)(g_th16 + (size_t)(b * S + qw + g) * 8 + tig * 2);
    u32 tA1 = *(const u32*)(g_th16 + (size_t)(b * S + qw + 8 + g) * 8 + tig * 2);

    // pass 1 (subsampled): approximate per-query row max
    float m0 = -1e30f, m1 = -1e30f;
#pragma unroll 4
    for (int cb = 0; cb < S4; cb += 64) {
        u32 bA = *(const u32*)(phi_s + (cb + g) * 8 + tig * 2);
        u32 bB = *(const u32*)(phi_s + (cb + 8 + g) * 8 + tig * 2);
        float c0[4] = {0.f, 0.f, 0.f, 0.f};
        float c1[4] = {0.f, 0.f, 0.f, 0.f};
        mma_16n8k8(c0, tA0, tA1, bA);
        mma_16n8k8(c1, tA0, tA1, bB);
        m0 = fmaxf(m0, fmaxf(fmaxf(c0[0], c0[1]), fmaxf(c1[0], c1[1])));
        m1 = fmaxf(m1, fmaxf(fmaxf(c0[2], c0[3]), fmaxf(c1[2], c1[3])));
    }
    m0 = fmaxf(m0, __shfl_xor_sync(0xFFFFFFFF, m0, 1));
    m0 = fmaxf(m0, __shfl_xor_sync(0xFFFFFFFF, m0, 2)) + 2.0f;
    m1 = fmaxf(m1, __shfl_xor_sync(0xFFFFFFFF, m1, 1));
    m1 = fmaxf(m1, __shfl_xor_sync(0xFFFFFFFF, m1, 2)) + 2.0f;
    const float nm0 = -m0, nm1 = -m1;

    // pass 2
    float o[4][4];
#pragma unroll
    for (int nt = 0; nt < 4; nt++)
#pragma unroll
        for (int j = 0; j < 4; j++) o[nt][j] = 0.f;
    float lacc[4] = {0.f, 0.f, 0.f, 0.f};
    const u32 ONES = 0x3C003C00u;

    for (int h = 0; h < 2; h++) {
        if (h == 1) {
            __syncthreads();
            for (int i = tid; i < 2048; i += 256) {
                int oc = i >> 6, j = i & 63;
                uint4 v = *(const uint4*)(g_g16 + ((size_t)b * 32 + oc) * S4 + 512 + j * 8);
                *(uint4*)(smem + G_OFF + oc * GROW + j * 16) = v;
            }
            __syncthreads();
        }
        const int key0 = h * 512;
#pragma unroll 2
        for (int cc = 0; cc < 512; cc += 16) {
            const int cb = key0 + cc;
            u32 bA = *(const u32*)(phi_s + (cb + g) * 8 + tig * 2);
            u32 bB = *(const u32*)(phi_s + (cb + 8 + g) * 8 + tig * 2);
            float c0[4] = {nm0, nm0, nm1, nm1};
            float c1[4] = {nm0, nm0, nm1, nm1};
            mma_16n8k8(c0, tA0, tA1, bA);
            mma_16n8k8(c1, tA0, tA1, bB);

            u32 pA0 = f16x2_of(ex2f(c0[0]), ex2f(c0[1]));
            u32 pA1 = f16x2_of(ex2f(c0[2]), ex2f(c0[3]));
            u32 pA2 = f16x2_of(ex2f(c1[0]), ex2f(c1[1]));
            u32 pA3 = f16x2_of(ex2f(c1[2]), ex2f(c1[3]));

            const char* gb = smem + G_OFF + cc * 2 + tig * 8;
#pragma unroll
            for (int nt = 0; nt < 4; nt++) {
                int oc = nt * 8 + g;
                ull bv = *(const ull*)(gb + oc * GROW);
                mma_16n8k16(o[nt], pA0, pA1, pA2, pA3, (u32)bv, (u32)(bv >> 32));
            }
            mma_16n8k16(lacc, pA0, pA1, pA2, pA3, ONES, ONES);
        }
    }

    __syncthreads();   // done with g -> region becomes out_s

    // ---- epilogue MMA3: out = (gamma/l) * (o @ w_o^T) ----
    const float gamma = gamma_p[0];
    const float inv0 = gamma / lacc[0];
    const float inv1 = gamma / lacc[2];

    u32 a3[2][4];
#pragma unroll
    for (int ks = 0; ks < 2; ks++) {
        const float* oA = o[2 * ks];
        const float* oB = o[2 * ks + 1];
        a3[ks][0] = f16x2_of(oA[0] * inv0, oA[1] * inv0);
        a3[ks][1] = f16x2_of(oA[2] * inv1, oA[3] * inv1);
        a3[ks][2] = f16x2_of(oB[0] * inv0, oB[1] * inv0);
        a3[ks][3] = f16x2_of(oB[2] * inv1, oB[3] * inv1);
    }
    const int r0 = w * 16 + g, r1 = r0 + 8;
#pragma unroll
    for (int nt3 = 0; nt3 < 8; nt3++) {
        int co = nt3 * 8 + g;
        float rc[4] = {0.f, 0.f, 0.f, 0.f};
#pragma unroll
        for (int ks = 0; ks < 2; ks++) {
            u32 b0 = *(const u32*)(wo16 + co * 36 + ks * 16 + tig * 2);
            u32 b1 = *(const u32*)(wo16 + co * 36 + ks * 16 + 8 + tig * 2);
            mma_16n8k16(rc, a3[ks][0], a3[ks][1], a3[ks][2], a3[ks][3], b0, b1);
        }
        int col = nt3 * 8 + tig * 2;
        out_s[r0 * 65 + col]     = rc[0];
        out_s[r0 * 65 + col + 1] = rc[1];
        out_s[r1 * 65 + col]     = rc[2];
        out_s[r1 * 65 + col + 1] = rc[3];
    }
    __syncthreads();

    // ---- coalesced residual-add writeback ----
    const float* xb = x + (size_t)b * CHAN * S;
    float* ob = out + (size_t)b * CHAN * S;
#pragma unroll 4
    for (int k = 0; k < 32; k++) {
        int i = tid + k * 256;
        int q = i & 127, ch = i >> 7;
        int s = q0b + q;
        ob[(size_t)ch * S + s] = out_s[q * 65 + ch] + xb[(size_t)ch * S + s];
    }
}

// ---------------------------------------------------------------------------
extern "C" void kernel_launch(void* const* d_in, const int* in_sizes, int n_in,
                              void* d_out, int out_size)
{
    const float* x       = (const float*)d_in[0];
    const float* w_theta = (const float*)d_in[1];
    const float* w_phi   = (const float*)d_in[2];
    const float* w_g     = (const float*)d_in[3];
    const float* w_o     = (const float*)d_in[4];
    const float* gamma   = (const float*)d_in[5];
    float* out = (float*)d_out;

    cudaFuncSetAttribute(prep_kernel, cudaFuncAttributeMaxDynamicSharedMemorySize, PREP_SMEM);
    prep_kernel<<<256, 256, PREP_SMEM>>>(x, w_theta, w_phi, w_g);

    cudaFuncSetAttribute(attn_hmma, cudaFuncAttributeMaxDynamicSharedMemorySize, SMEM_REQ);
    attn_hmma<<<512, 256, SMEM_REQ>>>(x, w_o, gamma, out);
}

// round 17
// speedup vs baseline: 3.6385x; 1.0050x over previous
#include <cuda_runtime.h>
#include <cuda_fp16.h>

typedef unsigned long long ull;
typedef unsigned int u32;

#define BATCH 16
#define CHAN  64
#define S     4096
#define S4    1024

__device__ __align__(16) __half g_phi16[BATCH * S4 * 8];  // [b][t][8]
__device__ __align__(16) __half g_g16[BATCH * 32 * S4];   // [b][oc][t] pair-interleaved
__device__ __align__(16) __half g_th16[BATCH * S * 8];    // [b][s][8] *log2e

// ---------------- helpers ----------------
__device__ __forceinline__ float ex2f(float a) {
    float r; asm("ex2.approx.ftz.f32 %0, %1;" : "=f"(r) : "f"(a)); return r;
}
__device__ __forceinline__ u32 f16x2_of(float lo, float hi) {
    u32 r; asm("cvt.rn.f16x2.f32 %0, %1, %2;" : "=r"(r) : "f"(hi), "f"(lo)); return r;
}
__device__ __forceinline__ u32 h2u(__half2 h) { return *reinterpret_cast<u32*>(&h); }
__device__ __forceinline__ ull pack2(float a, float b) {
    ull r; asm("mov.b64 %0, {%1, %2};" : "=l"(r) : "f"(a), "f"(b)); return r;
}
__device__ __forceinline__ void unpack2(ull v, float& a, float& b) {
    asm("mov.b64 {%0, %1}, %2;" : "=f"(a), "=f"(b) : "l"(v));
}
__device__ __forceinline__ ull ffma2(ull a, ull b, ull c) {
    ull d; asm("fma.rn.f32x2 %0, %1, %2, %3;" : "=l"(d) : "l"(a), "l"(b), "l"(c)); return d;
}
__device__ __forceinline__ ull d2u(double d) { return __double_as_longlong(d); }

// pair-interleave within each 16-key chunk: u32 j -> slot ((j&3)<<1)|(j>>2)
__device__ __forceinline__ int gidx16(int t) {
    int wi = t & 15, j = wi >> 1, lo = wi & 1;
    int j2 = ((j & 3) << 1) | (j >> 2);
    return (t & ~15) | (j2 << 1) | lo;
}

__device__ __forceinline__ void mma_16n8k8(float* c, u32 a0, u32 a1, u32 b0) {
    asm volatile("mma.sync.aligned.m16n8k8.row.col.f32.f16.f16.f32 "
        "{%0,%1,%2,%3}, {%4,%5}, {%6}, {%0,%1,%2,%3};"
        : "+f"(c[0]), "+f"(c[1]), "+f"(c[2]), "+f"(c[3])
        : "r"(a0), "r"(a1), "r"(b0));
}
__device__ __forceinline__ void mma_16n8k16(float* c, u32 a0, u32 a1, u32 a2, u32 a3,
                                            u32 b0, u32 b1) {
    asm volatile("mma.sync.aligned.m16n8k16.row.col.f32.f16.f16.f32 "
        "{%0,%1,%2,%3}, {%4,%5,%6,%7}, {%8,%9}, {%0,%1,%2,%3};"
        : "+f"(c[0]), "+f"(c[1]), "+f"(c[2]), "+f"(c[3])
        : "r"(a0), "r"(a1), "r"(a2), "r"(a3), "r"(b0), "r"(b1));
}

// prep kernel dynamic smem
#define PREP_XS_OFF 0
#define PREP_WS_OFF 65536
#define PREP_SMEM   90112

// ---------------------------------------------------------------------------
// Fused prep: 1x1 convs (theta 8, phi 8, g 32) + 2x2 maxpool for phi/g.
// ---------------------------------------------------------------------------
__global__ void __launch_bounds__(256, 2) prep_kernel(
    const float* __restrict__ x, const float* __restrict__ w_theta,
    const float* __restrict__ w_phi, const float* __restrict__ w_g)
{
    extern __shared__ char psm[];
    float* xs = (float*)(psm + PREP_XS_OFF);
    ull*   ws = (ull*)(psm + PREP_WS_OFF);

    const int tid = threadIdx.x;
    const int b   = blockIdx.x >> 4;
    const int rt  = blockIdx.x & 15;

    {
        const float4* src = (const float4*)(x + (size_t)b * CHAN * S + rt * 256);
        for (int i = tid; i < 4096; i += 256) {
            int c = i >> 6, f = i & 63;
            ((float4*)xs)[i] = src[c * (S / 4) + f];
        }
    }
    for (int i = tid; i < 3072; i += 256) {
        int u = i >> 6, c = i & 63;
        float w;
        if (u < 8)        w = w_theta[u * 64 + c] * 1.4426950408889634f;
        else if (u < 16)  w = w_phi[(u - 8) * 64 + c];
        else              w = w_g[(u - 16) * 64 + c];
        ws[i] = pack2(w, w);
    }
    __syncthreads();

    const int pos = tid & 63, ogrp = tid >> 6;
    const int pr = pos >> 5, pc = pos & 31;
    const int u0 = ogrp * 12;

    ull acc[12][2];
#pragma unroll
    for (int j = 0; j < 12; j++) acc[j][0] = acc[j][1] = 0ull;

    const float* xp = xs + (2 * pr) * 64 + 2 * pc;
    const ull* wp = ws + u0 * 64;
#pragma unroll 2
    for (int c = 0; c < CHAN; c++) {
        ull a0 = *(const ull*)(xp + c * 256);
        ull a1 = *(const ull*)(xp + c * 256 + 64);
#pragma unroll
        for (int j = 0; j < 12; j++) {
            ull w = wp[j * 64 + c];
            acc[j][0] = ffma2(a0, w, acc[j][0]);
            acc[j][1] = ffma2(a1, w, acc[j][1]);
        }
    }

    float v[12][4];
#pragma unroll
    for (int j = 0; j < 12; j++) {
        unpack2(acc[j][0], v[j][0], v[j][1]);
        unpack2(acc[j][1], v[j][2], v[j][3]);
    }

    const int t = (rt * 2 + pr) * 32 + pc;
    const int ti = gidx16(t);
    const int h0 = rt * 4 + 2 * pr, w0c = 2 * pc;

    if (ogrp == 0) {
#pragma unroll
        for (int px = 0; px < 4; px++) {
            int s = (h0 + (px >> 1)) * 64 + w0c + (px & 1);
            uint4 o;
            o.x = f16x2_of(v[0][px], v[1][px]);
            o.y = f16x2_of(v[2][px], v[3][px]);
            o.z = f16x2_of(v[4][px], v[5][px]);
            o.w = f16x2_of(v[6][px], v[7][px]);
            *(uint4*)(g_th16 + (size_t)(b * S + s) * 8) = o;
        }
        float m[4];
#pragma unroll
        for (int j = 8; j < 12; j++)
            m[j - 8] = fmaxf(fmaxf(v[j][0], v[j][1]), fmaxf(v[j][2], v[j][3]));
        uint2 o;
        o.x = f16x2_of(m[0], m[1]);
        o.y = f16x2_of(m[2], m[3]);
        *(uint2*)(g_phi16 + (size_t)(b * S4 + t) * 8) = o;
    } else if (ogrp == 1) {
        float m[4];
#pragma unroll
        for (int j = 0; j < 4; j++)
            m[j] = fmaxf(fmaxf(v[j][0], v[j][1]), fmaxf(v[j][2], v[j][3]));
        uint2 o;
        o.x = f16x2_of(m[0], m[1]);
        o.y = f16x2_of(m[2], m[3]);
        *(uint2*)(g_phi16 + (size_t)(b * S4 + t) * 8 + 4) = o;
#pragma unroll
        for (int j = 4; j < 12; j++) {
            float mm = fmaxf(fmaxf(v[j][0], v[j][1]), fmaxf(v[j][2], v[j][3]));
            g_g16[((size_t)b * 32 + (j - 4)) * S4 + ti] = __float2half(mm);
        }
    } else {
        int oc0 = (ogrp == 2) ? 8 : 20;
#pragma unroll
        for (int j = 0; j < 12; j++) {
            float mm = fmaxf(fmaxf(v[j][0], v[j][1]), fmaxf(v[j][2], v[j][3]));
            g_g16[((size_t)b * 32 + oc0 + j) * S4 + ti] = __float2half(mm);
        }
    }
}

// attention smem offsets
#define PHI_OFF  0                 // 16384 B
#define G_OFF    16384             // 32 oc * GROW = 33280 B
#define GROW     1040
#define WO16_OFF 49664             // fp16 w_o [64][36] = 4608 B
#define SMEM_REQ 54272
#define OUT_OFF  G_OFF             // result staging [128 q][65 floats]

// ---------------------------------------------------------------------------
// Attention: warp-level HMMA flash, 4 CTAs/SM, software-pipelined pass 2:
//  phi fragments prefetched one chunk ahead; g fragments hoisted before ex2.
// ---------------------------------------------------------------------------
__global__ void __launch_bounds__(256, 4) attn_hmma(
    const float* __restrict__ x, const float* __restrict__ w_o,
    const float* __restrict__ gamma_p, float* __restrict__ out)
{
    extern __shared__ char smem[];
    __half* phi_s = (__half*)(smem + PHI_OFF);
    __half* wo16  = (__half*)(smem + WO16_OFF);
    float*  out_s = (float*)(smem + OUT_OFF);

    const int tid = threadIdx.x;
    const int w   = tid >> 5;
    const int lane = tid & 31;
    const int g   = lane >> 2;
    const int tig = lane & 3;
    const int b   = blockIdx.x >> 5;
    const int q0b = (blockIdx.x & 31) * 128;
    const int qw  = q0b + w * 16;

    {
        const uint4* src = (const uint4*)(g_phi16 + (size_t)b * S4 * 8);
        uint4* dst = (uint4*)phi_s;
        for (int i = tid; i < 1024; i += 256) dst[i] = src[i];
    }
    for (int i = tid; i < 2048; i += 256) {
        int oc = i >> 6, j = i & 63;
        uint4 v = *(const uint4*)(g_g16 + ((size_t)b * 32 + oc) * S4 + j * 8);
        *(uint4*)(smem + G_OFF + oc * GROW + j * 16) = v;
    }
    for (int i = tid; i < 2048; i += 256) {
        int co = i >> 5, k = i & 31;
        wo16[co * 36 + k] = __float2half(w_o[co * 32 + k]);
    }
    __syncthreads();

    u32 tA0 = *(const u32*)(g_th16 + (size_t)(b * S + qw + g) * 8 + tig * 2);
    u32 tA1 = *(const u32*)(g_th16 + (size_t)(b * S + qw + 8 + g) * 8 + tig * 2);

    // pass 1 (subsampled): approximate per-query row max
    float m0 = -1e30f, m1 = -1e30f;
#pragma unroll 4
    for (int cb = 0; cb < S4; cb += 64) {
        u32 bA = *(const u32*)(phi_s + (cb + g) * 8 + tig * 2);
        u32 bB = *(const u32*)(phi_s + (cb + 8 + g) * 8 + tig * 2);
        float c0[4] = {0.f, 0.f, 0.f, 0.f};
        float c1[4] = {0.f, 0.f, 0.f, 0.f};
        mma_16n8k8(c0, tA0, tA1, bA);
        mma_16n8k8(c1, tA0, tA1, bB);
        m0 = fmaxf(m0, fmaxf(fmaxf(c0[0], c0[1]), fmaxf(c1[0], c1[1])));
        m1 = fmaxf(m1, fmaxf(fmaxf(c0[2], c0[3]), fmaxf(c1[2], c1[3])));
    }
    m0 = fmaxf(m0, __shfl_xor_sync(0xFFFFFFFF, m0, 1));
    m0 = fmaxf(m0, __shfl_xor_sync(0xFFFFFFFF, m0, 2)) + 2.0f;
    m1 = fmaxf(m1, __shfl_xor_sync(0xFFFFFFFF, m1, 1));
    m1 = fmaxf(m1, __shfl_xor_sync(0xFFFFFFFF, m1, 2)) + 2.0f;
    const float nm0 = -m0, nm1 = -m1;

    // pass 2: software-pipelined over 16-key chunks
    float o[4][4];
#pragma unroll
    for (int nt = 0; nt < 4; nt++)
#pragma unroll
        for (int j = 0; j < 4; j++) o[nt][j] = 0.f;
    float lacc[4] = {0.f, 0.f, 0.f, 0.f};
    const u32 ONES = 0x3C003C00u;
    const __half* phw = phi_s + g * 8 + tig * 2;   // warp-lane phi base

    for (int h = 0; h < 2; h++) {
        if (h == 1) {
            __syncthreads();
            for (int i = tid; i < 2048; i += 256) {
                int oc = i >> 6, j = i & 63;
                uint4 v = *(const uint4*)(g_g16 + ((size_t)b * 32 + oc) * S4 + 512 + j * 8);
                *(uint4*)(smem + G_OFF + oc * GROW + j * 16) = v;
            }
            __syncthreads();
        }
        const int key0 = h * 512;
        // prime the phi prefetch
        u32 nbA = *(const u32*)(phw + (size_t)key0 * 8);
        u32 nbB = *(const u32*)(phw + (size_t)(key0 + 8) * 8);
#pragma unroll 2
        for (int cc = 0; cc < 512; cc += 16) {
            u32 bA = nbA, bB = nbB;
            float c0[4] = {nm0, nm0, nm1, nm1};
            float c1[4] = {nm0, nm0, nm1, nm1};
            mma_16n8k8(c0, tA0, tA1, bA);
            mma_16n8k8(c1, tA0, tA1, bB);

            // prefetch next chunk's phi fragments (hidden under ex2 chain)
            if (cc < 496) {
                nbA = *(const u32*)(phw + (size_t)(key0 + cc + 16) * 8);
                nbB = *(const u32*)(phw + (size_t)(key0 + cc + 24) * 8);
            }
            // hoist all g fragments (independent of scores; overlap MUFU)
            const char* gb = smem + G_OFF + cc * 2 + tig * 8;
            ull bv0 = *(const ull*)(gb + g * GROW);
            ull bv1 = *(const ull*)(gb + (8 + g) * GROW);
            ull bv2 = *(const ull*)(gb + (16 + g) * GROW);
            ull bv3 = *(const ull*)(gb + (24 + g) * GROW);

            u32 pA0 = f16x2_of(ex2f(c0[0]), ex2f(c0[1]));
            u32 pA1 = f16x2_of(ex2f(c0[2]), ex2f(c0[3]));
            u32 pA2 = f16x2_of(ex2f(c1[0]), ex2f(c1[1]));
            u32 pA3 = f16x2_of(ex2f(c1[2]), ex2f(c1[3]));

            mma_16n8k16(o[0], pA0, pA1, pA2, pA3, (u32)bv0, (u32)(bv0 >> 32));
            mma_16n8k16(o[1], pA0, pA1, pA2, pA3, (u32)bv1, (u32)(bv1 >> 32));
            mma_16n8k16(o[2], pA0, pA1, pA2, pA3, (u32)bv2, (u32)(bv2 >> 32));
            mma_16n8k16(o[3], pA0, pA1, pA2, pA3, (u32)bv3, (u32)(bv3 >> 32));
            mma_16n8k16(lacc, pA0, pA1, pA2, pA3, ONES, ONES);
        }
    }

    __syncthreads();   // done with g -> region becomes out_s

    // ---- epilogue MMA3: out = (gamma/l) * (o @ w_o^T) ----
    const float gamma = gamma_p[0];
    const float inv0 = gamma / lacc[0];
    const float inv1 = gamma / lacc[2];

    u32 a3[2][4];
#pragma unroll
    for (int ks = 0; ks < 2; ks++) {
        const float* oA = o[2 * ks];
        const float* oB = o[2 * ks + 1];
        a3[ks][0] = f16x2_of(oA[0] * inv0, oA[1] * inv0);
        a3[ks][1] = f16x2_of(oA[2] * inv1, oA[3] * inv1);
        a3[ks][2] = f16x2_of(oB[0] * inv0, oB[1] * inv0);
        a3[ks][3] = f16x2_of(oB[2] * inv1, oB[3] * inv1);
    }
    const int r0 = w * 16 + g, r1 = r0 + 8;
#pragma unroll
    for (int nt3 = 0; nt3 < 8; nt3++) {
        int co = nt3 * 8 + g;
        float rc[4] = {0.f, 0.f, 0.f, 0.f};
#pragma unroll
        for (int ks = 0; ks < 2; ks++) {
            u32 b0 = *(const u32*)(wo16 + co * 36 + ks * 16 + tig * 2);
            u32 b1 = *(const u32*)(wo16 + co * 36 + ks * 16 + 8 + tig * 2);
            mma_16n8k16(rc, a3[ks][0], a3[ks][1], a3[ks][2], a3[ks][3], b0, b1);
        }
        int col = nt3 * 8 + tig * 2;
        out_s[r0 * 65 + col]     = rc[0];
        out_s[r0 * 65 + col + 1] = rc[1];
        out_s[r1 * 65 + col]     = rc[2];
        out_s[r1 * 65 + col + 1] = rc[3];
    }
    __syncthreads();

    // ---- coalesced residual-add writeback ----
    const float* xb = x + (size_t)b * CHAN * S;
    float* ob = out + (size_t)b * CHAN * S;
#pragma unroll 4
    for (int k = 0; k < 32; k++) {
        int i = tid + k * 256;
        int q = i & 127, ch = i >> 7;
        int s = q0b + q;
        ob[(size_t)ch * S + s] = out_s[q * 65 + ch] + xb[(size_t)ch * S + s];
    }
}

// ---------------------------------------------------------------------------
extern "C" void kernel_launch(void* const* d_in, const int* in_sizes, int n_in,
                              void* d_out, int out_size)
{
    const float* x       = (const float*)d_in[0];
    const float* w_theta = (const float*)d_in[1];
    const float* w_phi   = (const float*)d_in[2];
    const float* w_g     = (const float*)d_in[3];
    const float* w_o     = (const float*)d_in[4];
    const float* gamma   = (const float*)d_in[5];
    float* out = (float*)d_out;

    cudaFuncSetAttribute(prep_kernel, cudaFuncAttributeMaxDynamicSharedMemorySize, PREP_SMEM);
    prep_kernel<<<256, 256, PREP_SMEM>>>(x, w_theta, w_phi, w_g);

    cudaFuncSetAttribute(attn_hmma, cudaFuncAttributeMaxDynamicSharedMemorySize, SMEM_REQ);
    attn_hmma<<<512, 256, SMEM_REQ>>>(x, w_o, gamma, out);
}